// round 2
// baseline (speedup 1.0000x reference)
#include <cuda_runtime.h>
#include <math.h>

// Problem dims
#define N_TOK 4096
#define C_DIM 512
#define NH 8
#define DH 64

// ---------------- scratch (device globals, no runtime alloc) ----------------
__device__ float  g_dist[(size_t)N_TOK * N_TOK];   // 64 MB haversine distances
__device__ float  g_q[NH * N_TOK * DH];            // 4 MB each, head-major [h][n][d]
__device__ float  g_k[NH * N_TOK * DH];
__device__ float  g_v[NH * N_TOK * DH];
__device__ float  g_o[NH * N_TOK * DH];
__device__ double g_sum;
__device__ double g_sumsq;
__device__ float  g_neg_inv_std;

// ---------------- kernel 0: zero accumulators ----------------
__global__ void init_kernel() {
    g_sum = 0.0;
    g_sumsq = 0.0;
}

// ---------------- kernel 1: haversine distance matrix + sum/sumsq ----------------
__global__ void dist_kernel(const float* __restrict__ lat, const float* __restrict__ lon) {
    int i = blockIdx.x;
    float lat_i = lat[i];
    float lon_i = lon[i];
    float cli = __cosf(lat_i);
    double s = 0.0, s2 = 0.0;
    for (int j = threadIdx.x; j < N_TOK; j += 256) {
        float latj = lat[j];
        float dlat = latj - lat_i;
        float dlon = lon[j] - lon_i;
        float sa = __sinf(0.5f * dlat);
        float sb = __sinf(0.5f * dlon);
        float a = sa * sa + cli * __cosf(latj) * (sb * sb);
        a = fminf(fmaxf(a, 0.0f), 1.0f);
        float d = 2.0f * asinf(sqrtf(a));
        g_dist[(size_t)i * N_TOK + j] = d;
        s += (double)d;
        s2 += (double)d * (double)d;
    }
    __shared__ double sh[256];
    __shared__ double sh2[256];
    sh[threadIdx.x] = s;
    sh2[threadIdx.x] = s2;
    __syncthreads();
    for (int off = 128; off > 0; off >>= 1) {
        if (threadIdx.x < off) {
            sh[threadIdx.x] += sh[threadIdx.x + off];
            sh2[threadIdx.x] += sh2[threadIdx.x + off];
        }
        __syncthreads();
    }
    if (threadIdx.x == 0) {
        atomicAdd(&g_sum, sh[0]);
        atomicAdd(&g_sumsq, sh2[0]);
    }
}

// ---------------- kernel 2: finalize std (ddof=1) ----------------
__global__ void finalize_kernel() {
    double M = (double)N_TOK * (double)N_TOK;
    double mean = g_sum / M;
    double var = (g_sumsq - g_sum * mean) / (M - 1.0);
    g_neg_inv_std = (float)(-1.0 / sqrt(var));
}

// ---------------- kernel 3: QKV projection GEMM + scatter ----------------
// C[i,j] = sum_k X[i,k] * Wq[j,k] + bq[j], scattered into g_q/g_k/g_v head-major.
// Grid: (1536/64, 4096/64), block 256 (16x16 logical).
__global__ void qkv_gemm(const float* __restrict__ X,
                         const float* __restrict__ Wq,
                         const float* __restrict__ bq) {
    __shared__ float Xt[16][68];
    __shared__ float Wt[16][68];
    int j0 = blockIdx.x * 64;
    int i0 = blockIdx.y * 64;
    int tid = threadIdx.x;
    int ty = tid >> 4, tx = tid & 15;
    int ty4 = ty * 4, tx4 = tx * 4;
    int li = tid >> 2;         // 0..63
    int lk = (tid & 3) * 4;    // 0,4,8,12

    float acc[4][4];
#pragma unroll
    for (int r = 0; r < 4; r++)
#pragma unroll
        for (int c = 0; c < 4; c++) acc[r][c] = 0.0f;

    for (int k0 = 0; k0 < C_DIM; k0 += 16) {
        float4 xa = *(const float4*)&X[(size_t)(i0 + li) * C_DIM + k0 + lk];
        float4 wa = *(const float4*)&Wq[(size_t)(j0 + li) * C_DIM + k0 + lk];
        __syncthreads();
        Xt[lk + 0][li] = xa.x; Xt[lk + 1][li] = xa.y;
        Xt[lk + 2][li] = xa.z; Xt[lk + 3][li] = xa.w;
        Wt[lk + 0][li] = wa.x; Wt[lk + 1][li] = wa.y;
        Wt[lk + 2][li] = wa.z; Wt[lk + 3][li] = wa.w;
        __syncthreads();
#pragma unroll
        for (int kk = 0; kk < 16; kk++) {
            float4 a = *(const float4*)&Xt[kk][ty4];
            float4 b = *(const float4*)&Wt[kk][tx4];
            float av[4] = {a.x, a.y, a.z, a.w};
            float bv[4] = {b.x, b.y, b.z, b.w};
#pragma unroll
            for (int r = 0; r < 4; r++)
#pragma unroll
                for (int c = 0; c < 4; c++) acc[r][c] += av[r] * bv[c];
        }
    }

    // epilogue: add bias, scatter to q/k/v head-major
    float4 bb = *(const float4*)&bq[j0 + tx4];
    float bv[4] = {bb.x, bb.y, bb.z, bb.w};
    int part = j0 / C_DIM;              // 0=q, 1=k, 2=v
    int h = (j0 % C_DIM) / DH;
    float* dst = (part == 0) ? g_q : ((part == 1) ? g_k : g_v);
    dst += (size_t)h * N_TOK * DH;
#pragma unroll
    for (int r = 0; r < 4; r++) {
        float4 o;
        o.x = acc[r][0] + bv[0];
        o.y = acc[r][1] + bv[1];
        o.z = acc[r][2] + bv[2];
        o.w = acc[r][3] + bv[3];
        *(float4*)&dst[(size_t)(i0 + ty4 + r) * DH + tx4] = o;
    }
}

// ---------------- kernel 4: flash attention (fp32) ----------------
// Grid: (4096/64, 8). Block 256 (16x16). BM=BN=64, dh=64.
__global__ void attn_kernel() {
    const int STR = 68;
    extern __shared__ float smem[];
    float* Qt = smem;                 // [64(d)][64(i)] transposed
    float* Kt = Qt + 64 * STR;        // [64(d)][64(j)] transposed
    float* Vs = Kt + 64 * STR;        // [64(j)][64(d)]
    float* Pt = Vs + 64 * STR;        // [64(j)][64(i)] transposed

    int h = blockIdx.y;
    int i0 = blockIdx.x * 64;
    int tid = threadIdx.x;
    int ty = tid >> 4, tx = tid & 15;
    int ty4 = ty * 4, tx4 = tx * 4;
    int li = tid >> 2;                 // 0..63 row for loads
    int dbase = (tid & 3) * 16;        // 0,16,32,48

    const float* Q = g_q + (size_t)h * N_TOK * DH;
    const float* K = g_k + (size_t)h * N_TOK * DH;
    const float* V = g_v + (size_t)h * N_TOK * DH;
    float nis = g_neg_inv_std;
    const float scale = 0.125f;       // 1/sqrt(64)

    // load Q tile transposed (once)
    {
        const float4* qrow = (const float4*)&Q[(size_t)(i0 + li) * DH + dbase];
#pragma unroll
        for (int q = 0; q < 4; q++) {
            float4 v4 = qrow[q];
            int d = dbase + q * 4;
            Qt[(d + 0) * STR + li] = v4.x;
            Qt[(d + 1) * STR + li] = v4.y;
            Qt[(d + 2) * STR + li] = v4.z;
            Qt[(d + 3) * STR + li] = v4.w;
        }
    }

    float m[4], l[4], o[4][4];
#pragma unroll
    for (int r = 0; r < 4; r++) {
        m[r] = -INFINITY;
        l[r] = 0.0f;
#pragma unroll
        for (int c = 0; c < 4; c++) o[r][c] = 0.0f;
    }

    for (int kb = 0; kb < N_TOK / 64; kb++) {
        int j0 = kb * 64;
        __syncthreads();   // prev iter done reading Kt/Vs; Qt stores visible after next barrier
        // load K (transposed) and V (direct)
        {
            const float4* krow = (const float4*)&K[(size_t)(j0 + li) * DH + dbase];
#pragma unroll
            for (int q = 0; q < 4; q++) {
                float4 v4 = krow[q];
                int d = dbase + q * 4;
                Kt[(d + 0) * STR + li] = v4.x;
                Kt[(d + 1) * STR + li] = v4.y;
                Kt[(d + 2) * STR + li] = v4.z;
                Kt[(d + 3) * STR + li] = v4.w;
            }
            const float4* vrow = (const float4*)&V[(size_t)(j0 + li) * DH + dbase];
#pragma unroll
            for (int q = 0; q < 4; q++) {
                float4 v4 = vrow[q];
                *(float4*)&Vs[li * STR + dbase + q * 4] = v4;
            }
        }
        __syncthreads();

        // S = Q @ K^T
        float s[4][4];
#pragma unroll
        for (int r = 0; r < 4; r++)
#pragma unroll
            for (int c = 0; c < 4; c++) s[r][c] = 0.0f;
#pragma unroll 8
        for (int d = 0; d < 64; d++) {
            float4 a = *(const float4*)&Qt[d * STR + ty4];
            float4 b = *(const float4*)&Kt[d * STR + tx4];
            float av[4] = {a.x, a.y, a.z, a.w};
            float bv[4] = {b.x, b.y, b.z, b.w};
#pragma unroll
            for (int r = 0; r < 4; r++)
#pragma unroll
                for (int c = 0; c < 4; c++) s[r][c] += av[r] * bv[c];
        }

        // scale + bias, online softmax
#pragma unroll
        for (int r = 0; r < 4; r++) {
            float4 d4 = *(const float4*)&g_dist[(size_t)(i0 + ty4 + r) * N_TOK + j0 + tx4];
            float dv[4] = {d4.x, d4.y, d4.z, d4.w};
#pragma unroll
            for (int c = 0; c < 4; c++) s[r][c] = s[r][c] * scale + dv[c] * nis;

            float mx = fmaxf(fmaxf(s[r][0], s[r][1]), fmaxf(s[r][2], s[r][3]));
#pragma unroll
            for (int off = 8; off > 0; off >>= 1)
                mx = fmaxf(mx, __shfl_xor_sync(0xffffffffu, mx, off, 16));
            float mnew = fmaxf(m[r], mx);
            float f = __expf(m[r] - mnew);
            m[r] = mnew;
            l[r] *= f;
#pragma unroll
            for (int c = 0; c < 4; c++) o[r][c] *= f;

            float rs = 0.0f;
#pragma unroll
            for (int c = 0; c < 4; c++) {
                float p = __expf(s[r][c] - mnew);
                s[r][c] = p;
                rs += p;
            }
#pragma unroll
            for (int off = 8; off > 0; off >>= 1)
                rs += __shfl_xor_sync(0xffffffffu, rs, off, 16);
            l[r] += rs;
        }

        // write P transposed to smem
#pragma unroll
        for (int r = 0; r < 4; r++)
#pragma unroll
            for (int c = 0; c < 4; c++)
                Pt[(tx4 + c) * STR + ty4 + r] = s[r][c];
        __syncthreads();

        // O += P @ V
#pragma unroll 8
        for (int j = 0; j < 64; j++) {
            float4 a = *(const float4*)&Pt[j * STR + ty4];
            float4 b = *(const float4*)&Vs[j * STR + tx4];
            float av[4] = {a.x, a.y, a.z, a.w};
            float bv[4] = {b.x, b.y, b.z, b.w};
#pragma unroll
            for (int r = 0; r < 4; r++)
#pragma unroll
                for (int c = 0; c < 4; c++) o[r][c] += av[r] * bv[c];
        }
    }

    // normalize and write out
    float* O = g_o + (size_t)h * N_TOK * DH;
#pragma unroll
    for (int r = 0; r < 4; r++) {
        float inv = 1.0f / l[r];
        float4 w;
        w.x = o[r][0] * inv;
        w.y = o[r][1] * inv;
        w.z = o[r][2] * inv;
        w.w = o[r][3] * inv;
        *(float4*)&O[(size_t)(i0 + ty4 + r) * DH + tx4] = w;
    }
}

// ---------------- kernel 5: output projection ----------------
// out[i,j] = sum_k Oflat[i,k] * Wo[j,k] + bo[j], Oflat[i,k] = g_o[(k/64)][i][k%64]
__global__ void out_gemm(const float* __restrict__ Wo,
                         const float* __restrict__ bo,
                         float* __restrict__ out) {
    __shared__ float At[16][68];
    __shared__ float Bt[16][68];
    int j0 = blockIdx.x * 64;
    int i0 = blockIdx.y * 64;
    int tid = threadIdx.x;
    int ty = tid >> 4, tx = tid & 15;
    int ty4 = ty * 4, tx4 = tx * 4;
    int li = tid >> 2;
    int lk = (tid & 3) * 4;

    float acc[4][4];
#pragma unroll
    for (int r = 0; r < 4; r++)
#pragma unroll
        for (int c = 0; c < 4; c++) acc[r][c] = 0.0f;

    for (int k0 = 0; k0 < C_DIM; k0 += 16) {
        int head = k0 >> 6;
        int kr = k0 & 63;
        float4 aa = *(const float4*)&g_o[(size_t)head * N_TOK * DH + (size_t)(i0 + li) * DH + kr + lk];
        float4 wa = *(const float4*)&Wo[(size_t)(j0 + li) * C_DIM + k0 + lk];
        __syncthreads();
        At[lk + 0][li] = aa.x; At[lk + 1][li] = aa.y;
        At[lk + 2][li] = aa.z; At[lk + 3][li] = aa.w;
        Bt[lk + 0][li] = wa.x; Bt[lk + 1][li] = wa.y;
        Bt[lk + 2][li] = wa.z; Bt[lk + 3][li] = wa.w;
        __syncthreads();
#pragma unroll
        for (int kk = 0; kk < 16; kk++) {
            float4 a = *(const float4*)&At[kk][ty4];
            float4 b = *(const float4*)&Bt[kk][tx4];
            float av[4] = {a.x, a.y, a.z, a.w};
            float bv[4] = {b.x, b.y, b.z, b.w};
#pragma unroll
            for (int r = 0; r < 4; r++)
#pragma unroll
                for (int c = 0; c < 4; c++) acc[r][c] += av[r] * bv[c];
        }
    }

    float4 bb = *(const float4*)&bo[j0 + tx4];
    float bv[4] = {bb.x, bb.y, bb.z, bb.w};
#pragma unroll
    for (int r = 0; r < 4; r++) {
        float4 o;
        o.x = acc[r][0] + bv[0];
        o.y = acc[r][1] + bv[1];
        o.z = acc[r][2] + bv[2];
        o.w = acc[r][3] + bv[3];
        *(float4*)&out[(size_t)(i0 + ty4 + r) * C_DIM + j0 + tx4] = o;
    }
}

// ---------------- launch ----------------
extern "C" void kernel_launch(void* const* d_in, const int* in_sizes, int n_in,
                              void* d_out, int out_size) {
    (void)in_sizes; (void)n_in; (void)out_size;
    const float* x     = (const float*)d_in[0];
    const float* lat   = (const float*)d_in[1];
    const float* lon   = (const float*)d_in[2];
    const float* w_qkv = (const float*)d_in[3];
    const float* b_qkv = (const float*)d_in[4];
    const float* w_out = (const float*)d_in[5];
    const float* b_out = (const float*)d_in[6];
    float* out = (float*)d_out;

    init_kernel<<<1, 1>>>();
    dist_kernel<<<N_TOK, 256>>>(lat, lon);
    finalize_kernel<<<1, 1>>>();
    qkv_gemm<<<dim3(3 * C_DIM / 64, N_TOK / 64), 256>>>(x, w_qkv, b_qkv);

    int attn_smem = 4 * 64 * 68 * (int)sizeof(float);  // 69632 B
    cudaFuncSetAttribute(attn_kernel, cudaFuncAttributeMaxDynamicSharedMemorySize, attn_smem);
    attn_kernel<<<dim3(N_TOK / 64, NH), 256, attn_smem>>>();

    out_gemm<<<dim3(C_DIM / 64, N_TOK / 64), 256>>>(w_out, b_out, out);
}

// round 5
// speedup vs baseline: 1.9922x; 1.9922x over previous
#include <cuda_runtime.h>
#include <math.h>
#include <stdint.h>

// Problem dims
#define N_TOK 4096
#define C_DIM 512
#define NH 8
#define DH 64

// ---------------- scratch (device globals, no runtime alloc) ----------------
__device__ float  g_dist[(size_t)N_TOK * N_TOK];   // 64 MB haversine distances
__device__ float  g_q[NH * N_TOK * DH];            // head-major [h][n][d], q pre-scaled by 1/8
__device__ float  g_k[NH * N_TOK * DH];
__device__ float  g_v[NH * N_TOK * DH];
__device__ float  g_o[NH * N_TOK * DH];
__device__ double g_sum;
__device__ double g_sumsq;
__device__ float  g_neg_inv_std;

// ---------------- helpers ----------------
__device__ __forceinline__ uint32_t f2tf(float f) {
    uint32_t r;
    asm("cvt.rna.tf32.f32 %0, %1;" : "=r"(r) : "f"(f));
    return r;
}
__device__ __forceinline__ void mma8(float c[4], const uint32_t a[4], uint32_t b0, uint32_t b1) {
    asm volatile(
        "mma.sync.aligned.m16n8k8.row.col.f32.tf32.tf32.f32 "
        "{%0,%1,%2,%3}, {%4,%5,%6,%7}, {%8,%9}, {%0,%1,%2,%3};"
        : "+f"(c[0]), "+f"(c[1]), "+f"(c[2]), "+f"(c[3])
        : "r"(a[0]), "r"(a[1]), "r"(a[2]), "r"(a[3]), "r"(b0), "r"(b1));
}

// ---------------- kernel 0: zero accumulators ----------------
__global__ void init_kernel() {
    g_sum = 0.0;
    g_sumsq = 0.0;
}

// ---------------- kernel 1: haversine distance matrix + sum/sumsq ----------------
__global__ void dist_kernel(const float* __restrict__ lat, const float* __restrict__ lon) {
    int i = blockIdx.x;
    float lat_i = lat[i];
    float lon_i = lon[i];
    float cli = __cosf(lat_i);
    double s = 0.0, s2 = 0.0;
    for (int j = threadIdx.x; j < N_TOK; j += 256) {
        float latj = lat[j];
        float dlat = latj - lat_i;
        float dlon = lon[j] - lon_i;
        float sa = __sinf(0.5f * dlat);
        float sb = __sinf(0.5f * dlon);
        float a = sa * sa + cli * __cosf(latj) * (sb * sb);
        a = fminf(fmaxf(a, 0.0f), 1.0f);
        float d = 2.0f * asinf(sqrtf(a));
        g_dist[(size_t)i * N_TOK + j] = d;
        s += (double)d;
        s2 += (double)d * (double)d;
    }
    __shared__ double sh[256];
    __shared__ double sh2[256];
    sh[threadIdx.x] = s;
    sh2[threadIdx.x] = s2;
    __syncthreads();
    for (int off = 128; off > 0; off >>= 1) {
        if (threadIdx.x < off) {
            sh[threadIdx.x] += sh[threadIdx.x + off];
            sh2[threadIdx.x] += sh2[threadIdx.x + off];
        }
        __syncthreads();
    }
    if (threadIdx.x == 0) {
        atomicAdd(&g_sum, sh[0]);
        atomicAdd(&g_sumsq, sh2[0]);
    }
}

// ---------------- kernel 2: finalize std (ddof=1) ----------------
__global__ void finalize_kernel() {
    double M = (double)N_TOK * (double)N_TOK;
    double mean = g_sum / M;
    double var = (g_sumsq - g_sum * mean) / (M - 1.0);
    g_neg_inv_std = (float)(-1.0 / sqrt(var));
}

// ---------------- kernel 3: QKV projection GEMM + scatter (fp32) ----------------
__global__ void qkv_gemm(const float* __restrict__ X,
                         const float* __restrict__ Wq,
                         const float* __restrict__ bq) {
    __shared__ float Xt[16][68];
    __shared__ float Wt[16][68];
    int j0 = blockIdx.x * 64;
    int i0 = blockIdx.y * 64;
    int tid = threadIdx.x;
    int ty = tid >> 4, tx = tid & 15;
    int ty4 = ty * 4, tx4 = tx * 4;
    int li = tid >> 2;
    int lk = (tid & 3) * 4;

    float acc[4][4];
#pragma unroll
    for (int r = 0; r < 4; r++)
#pragma unroll
        for (int c = 0; c < 4; c++) acc[r][c] = 0.0f;

    for (int k0 = 0; k0 < C_DIM; k0 += 16) {
        float4 xa = *(const float4*)&X[(size_t)(i0 + li) * C_DIM + k0 + lk];
        float4 wa = *(const float4*)&Wq[(size_t)(j0 + li) * C_DIM + k0 + lk];
        __syncthreads();
        Xt[lk + 0][li] = xa.x; Xt[lk + 1][li] = xa.y;
        Xt[lk + 2][li] = xa.z; Xt[lk + 3][li] = xa.w;
        Wt[lk + 0][li] = wa.x; Wt[lk + 1][li] = wa.y;
        Wt[lk + 2][li] = wa.z; Wt[lk + 3][li] = wa.w;
        __syncthreads();
#pragma unroll
        for (int kk = 0; kk < 16; kk++) {
            float4 a = *(const float4*)&Xt[kk][ty4];
            float4 b = *(const float4*)&Wt[kk][tx4];
            float av[4] = {a.x, a.y, a.z, a.w};
            float bv[4] = {b.x, b.y, b.z, b.w};
#pragma unroll
            for (int r = 0; r < 4; r++)
#pragma unroll
                for (int c = 0; c < 4; c++) acc[r][c] += av[r] * bv[c];
        }
    }

    float4 bb = *(const float4*)&bq[j0 + tx4];
    float bv[4] = {bb.x, bb.y, bb.z, bb.w};
    int part = j0 / C_DIM;              // 0=q, 1=k, 2=v
    int h = (j0 % C_DIM) / DH;
    float* dst = (part == 0) ? g_q : ((part == 1) ? g_k : g_v);
    float sc = (part == 0) ? 0.125f : 1.0f;   // fold attn scale into Q
    dst += (size_t)h * N_TOK * DH;
#pragma unroll
    for (int r = 0; r < 4; r++) {
        float4 o;
        o.x = (acc[r][0] + bv[0]) * sc;
        o.y = (acc[r][1] + bv[1]) * sc;
        o.z = (acc[r][2] + bv[2]) * sc;
        o.w = (acc[r][3] + bv[3]) * sc;
        *(float4*)&dst[(size_t)(i0 + ty4 + r) * DH + tx4] = o;
    }
}

// ---------------- kernel 4: flash attention via mma.sync tf32 ----------------
// Grid (32, 8), 256 threads (8 warps). BM=128 (16 rows/warp), BN=64, dh=64.
// SMEM (uint32 words): Qs[128][68] | Ks[64][68] | Vs[64][68] | Ps[128][68]
#define QS_OFF 0
#define KS_OFF (128 * 68)
#define VS_OFF (KS_OFF + 64 * 68)
#define PS_OFF (VS_OFF + 64 * 68)
#define ATTN_SMEM_WORDS (PS_OFF + 128 * 68)
#define ATTN_SMEM_BYTES (ATTN_SMEM_WORDS * 4)

__global__ void __launch_bounds__(256, 2) attn_mma() {
    extern __shared__ uint32_t sm4[];
    uint32_t* Qs = sm4 + QS_OFF;
    uint32_t* Ks = sm4 + KS_OFF;
    uint32_t* Vs = sm4 + VS_OFF;
    uint32_t* Ps = sm4 + PS_OFF;

    int tid = threadIdx.x;
    int warp = tid >> 5;
    int lane = tid & 31;
    int gid = lane >> 2;       // 0..7
    int tig = lane & 3;        // 0..3
    int w16 = warp * 16;
    int h = blockIdx.y;
    int i0 = blockIdx.x * 128;
    float nis = g_neg_inv_std;

    const float* Q = g_q + (size_t)h * N_TOK * DH;
    const float* K = g_k + (size_t)h * N_TOK * DH;
    const float* V = g_v + (size_t)h * N_TOK * DH;

    // stage Q tile (128x64 -> tf32 smem, stride 68)
    {
        int r = tid >> 4;
        int c = (tid & 15) * 4;
#pragma unroll
        for (int p = 0; p < 8; p++) {
            int row = r + p * 16;
            float4 q4 = *(const float4*)&Q[(size_t)(i0 + row) * DH + c];
            uint4 t;
            t.x = f2tf(q4.x); t.y = f2tf(q4.y); t.z = f2tf(q4.z); t.w = f2tf(q4.w);
            *(uint4*)&Qs[row * 68 + c] = t;
        }
    }

    float m0 = -INFINITY, m1 = -INFINITY, l0 = 0.0f, l1 = 0.0f;
    float o[8][4];
#pragma unroll
    for (int n = 0; n < 8; n++)
#pragma unroll
        for (int q = 0; q < 4; q++) o[n][q] = 0.0f;

    const float* d0base = g_dist + (size_t)(i0 + w16 + gid) * N_TOK + 2 * tig;
    const float* d1base = d0base + (size_t)8 * N_TOK;

    for (int kb = 0; kb < N_TOK / 64; kb++) {
        int j0 = kb * 64;
        __syncthreads();
        // stage K, V tiles (64x64 each)
        {
            int r = tid >> 4;
            int c = (tid & 15) * 4;
#pragma unroll
            for (int p = 0; p < 4; p++) {
                int row = r + p * 16;
                float4 k4 = *(const float4*)&K[(size_t)(j0 + row) * DH + c];
                uint4 tk;
                tk.x = f2tf(k4.x); tk.y = f2tf(k4.y); tk.z = f2tf(k4.z); tk.w = f2tf(k4.w);
                *(uint4*)&Ks[row * 68 + c] = tk;
                float4 v4 = *(const float4*)&V[(size_t)(j0 + row) * DH + c];
                uint4 tv;
                tv.x = f2tf(v4.x); tv.y = f2tf(v4.y); tv.z = f2tf(v4.z); tv.w = f2tf(v4.w);
                *(uint4*)&Vs[row * 68 + c] = tv;
            }
        }
        __syncthreads();

        // S = Q @ K^T (per warp: 16x64)
        float s[8][4];
#pragma unroll
        for (int n = 0; n < 8; n++)
#pragma unroll
            for (int q = 0; q < 4; q++) s[n][q] = 0.0f;

#pragma unroll
        for (int k = 0; k < 8; k++) {
            uint32_t a[4];
            int k8 = k * 8 + tig;
            a[0] = Qs[(w16 + gid) * 68 + k8];
            a[1] = Qs[(w16 + gid + 8) * 68 + k8];
            a[2] = Qs[(w16 + gid) * 68 + k8 + 4];
            a[3] = Qs[(w16 + gid + 8) * 68 + k8 + 4];
#pragma unroll
            for (int n = 0; n < 8; n++) {
                uint32_t b0 = Ks[(n * 8 + gid) * 68 + k8];
                uint32_t b1 = Ks[(n * 8 + gid) * 68 + k8 + 4];
                mma8(s[n], a, b0, b1);
            }
        }

        // bias + row max
        float mx0 = -INFINITY, mx1 = -INFINITY;
#pragma unroll
        for (int n = 0; n < 8; n++) {
            float2 b0v = *(const float2*)(d0base + j0 + n * 8);
            float2 b1v = *(const float2*)(d1base + j0 + n * 8);
            s[n][0] += b0v.x * nis;
            s[n][1] += b0v.y * nis;
            s[n][2] += b1v.x * nis;
            s[n][3] += b1v.y * nis;
            mx0 = fmaxf(mx0, fmaxf(s[n][0], s[n][1]));
            mx1 = fmaxf(mx1, fmaxf(s[n][2], s[n][3]));
        }
        mx0 = fmaxf(mx0, __shfl_xor_sync(0xffffffffu, mx0, 1));
        mx0 = fmaxf(mx0, __shfl_xor_sync(0xffffffffu, mx0, 2));
        mx1 = fmaxf(mx1, __shfl_xor_sync(0xffffffffu, mx1, 1));
        mx1 = fmaxf(mx1, __shfl_xor_sync(0xffffffffu, mx1, 2));

        float mn0 = fmaxf(m0, mx0);
        float mn1 = fmaxf(m1, mx1);
        float f0 = __expf(m0 - mn0);
        float f1 = __expf(m1 - mn1);
        m0 = mn0; m1 = mn1;
        l0 *= f0; l1 *= f1;

        float sum0 = 0.0f, sum1 = 0.0f;
#pragma unroll
        for (int n = 0; n < 8; n++) {
            float p00 = __expf(s[n][0] - mn0);
            float p01 = __expf(s[n][1] - mn0);
            float p10 = __expf(s[n][2] - mn1);
            float p11 = __expf(s[n][3] - mn1);
            uint32_t t00 = f2tf(p00), t01 = f2tf(p01);
            uint32_t t10 = f2tf(p10), t11 = f2tf(p11);
            sum0 += __uint_as_float(t00) + __uint_as_float(t01);
            sum1 += __uint_as_float(t10) + __uint_as_float(t11);
            *(uint2*)&Ps[(w16 + gid) * 68 + n * 8 + 2 * tig] = make_uint2(t00, t01);
            *(uint2*)&Ps[(w16 + gid + 8) * 68 + n * 8 + 2 * tig] = make_uint2(t10, t11);
            o[n][0] *= f0; o[n][1] *= f0;
            o[n][2] *= f1; o[n][3] *= f1;
        }
        l0 += sum0;   // per-thread partial over this thread's 16 cols
        l1 += sum1;

        __syncwarp();

        // O += P @ V (per warp: 16x64)
#pragma unroll
        for (int k = 0; k < 8; k++) {
            uint32_t a[4];
            int k8 = k * 8 + tig;
            a[0] = Ps[(w16 + gid) * 68 + k8];
            a[1] = Ps[(w16 + gid + 8) * 68 + k8];
            a[2] = Ps[(w16 + gid) * 68 + k8 + 4];
            a[3] = Ps[(w16 + gid + 8) * 68 + k8 + 4];
#pragma unroll
            for (int n = 0; n < 8; n++) {
                uint32_t b0 = Vs[(k * 8 + tig) * 68 + n * 8 + gid];
                uint32_t b1 = Vs[(k * 8 + tig + 4) * 68 + n * 8 + gid];
                mma8(o[n], a, b0, b1);
            }
        }
    }

    // reduce l across quad, normalize, store
    l0 += __shfl_xor_sync(0xffffffffu, l0, 1);
    l0 += __shfl_xor_sync(0xffffffffu, l0, 2);
    l1 += __shfl_xor_sync(0xffffffffu, l1, 1);
    l1 += __shfl_xor_sync(0xffffffffu, l1, 2);
    float inv0 = 1.0f / l0;
    float inv1 = 1.0f / l1;

    float* O = g_o + ((size_t)h * N_TOK + i0) * DH;
#pragma unroll
    for (int n = 0; n < 8; n++) {
        float2 w0;
        w0.x = o[n][0] * inv0;
        w0.y = o[n][1] * inv0;
        *(float2*)&O[(size_t)(w16 + gid) * DH + n * 8 + 2 * tig] = w0;
        float2 w1;
        w1.x = o[n][2] * inv1;
        w1.y = o[n][3] * inv1;
        *(float2*)&O[(size_t)(w16 + gid + 8) * DH + n * 8 + 2 * tig] = w1;
    }
}

// ---------------- kernel 5: output projection (fp32) ----------------
__global__ void out_gemm(const float* __restrict__ Wo,
                         const float* __restrict__ bo,
                         float* __restrict__ out) {
    __shared__ float At[16][68];
    __shared__ float Bt[16][68];
    int j0 = blockIdx.x * 64;
    int i0 = blockIdx.y * 64;
    int tid = threadIdx.x;
    int ty = tid >> 4, tx = tid & 15;
    int ty4 = ty * 4, tx4 = tx * 4;
    int li = tid >> 2;
    int lk = (tid & 3) * 4;

    float acc[4][4];
#pragma unroll
    for (int r = 0; r < 4; r++)
#pragma unroll
        for (int c = 0; c < 4; c++) acc[r][c] = 0.0f;

    for (int k0 = 0; k0 < C_DIM; k0 += 16) {
        int head = k0 >> 6;
        int kr = k0 & 63;
        float4 aa = *(const float4*)&g_o[(size_t)head * N_TOK * DH + (size_t)(i0 + li) * DH + kr + lk];
        float4 wa = *(const float4*)&Wo[(size_t)(j0 + li) * C_DIM + k0 + lk];
        __syncthreads();
        At[lk + 0][li] = aa.x; At[lk + 1][li] = aa.y;
        At[lk + 2][li] = aa.z; At[lk + 3][li] = aa.w;
        Bt[lk + 0][li] = wa.x; Bt[lk + 1][li] = wa.y;
        Bt[lk + 2][li] = wa.z; Bt[lk + 3][li] = wa.w;
        __syncthreads();
#pragma unroll
        for (int kk = 0; kk < 16; kk++) {
            float4 a = *(const float4*)&At[kk][ty4];
            float4 b = *(const float4*)&Bt[kk][tx4];
            float av[4] = {a.x, a.y, a.z, a.w};
            float bv[4] = {b.x, b.y, b.z, b.w};
#pragma unroll
            for (int r = 0; r < 4; r++)
#pragma unroll
                for (int c = 0; c < 4; c++) acc[r][c] += av[r] * bv[c];
        }
    }

    float4 bb = *(const float4*)&bo[j0 + tx4];
    float bv[4] = {bb.x, bb.y, bb.z, bb.w};
#pragma unroll
    for (int r = 0; r < 4; r++) {
        float4 o;
        o.x = acc[r][0] + bv[0];
        o.y = acc[r][1] + bv[1];
        o.z = acc[r][2] + bv[2];
        o.w = acc[r][3] + bv[3];
        *(float4*)&out[(size_t)(i0 + ty4 + r) * C_DIM + j0 + tx4] = o;
    }
}

// ---------------- launch ----------------
extern "C" void kernel_launch(void* const* d_in, const int* in_sizes, int n_in,
                              void* d_out, int out_size) {
    (void)in_sizes; (void)n_in; (void)out_size;
    const float* x     = (const float*)d_in[0];
    const float* lat   = (const float*)d_in[1];
    const float* lon   = (const float*)d_in[2];
    const float* w_qkv = (const float*)d_in[3];
    const float* b_qkv = (const float*)d_in[4];
    const float* w_out = (const float*)d_in[5];
    const float* b_out = (const float*)d_in[6];
    float* out = (float*)d_out;

    init_kernel<<<1, 1>>>();
    dist_kernel<<<N_TOK, 256>>>(lat, lon);
    finalize_kernel<<<1, 1>>>();
    qkv_gemm<<<dim3(3 * C_DIM / 64, N_TOK / 64), 256>>>(x, w_qkv, b_qkv);

    cudaFuncSetAttribute(attn_mma, cudaFuncAttributeMaxDynamicSharedMemorySize, ATTN_SMEM_BYTES);
    attn_mma<<<dim3(N_TOK / 128, NH), 256, ATTN_SMEM_BYTES>>>();

    out_gemm<<<dim3(C_DIM / 64, N_TOK / 64), 256>>>(w_out, b_out, out);
}

// round 7
// speedup vs baseline: 2.2124x; 1.1105x over previous
#include <cuda_runtime.h>
#include <math.h>
#include <stdint.h>

// Problem dims
#define N_TOK 4096
#define C_DIM 512
#define NH 8
#define DH 64

// ---------------- scratch (device globals, no runtime alloc) ----------------
__device__ float  g_dist[(size_t)N_TOK * N_TOK];   // 64 MB haversine distances
__device__ float  g_q[NH * N_TOK * DH];            // head-major [h][n][d], q pre-scaled by 1/8
__device__ float  g_k[NH * N_TOK * DH];
__device__ float  g_v[NH * N_TOK * DH];
__device__ float  g_o[NH * N_TOK * DH];
__device__ double g_sum;
__device__ double g_sumsq;
__device__ float  g_neg_inv_std;

// ---------------- helpers ----------------
__device__ __forceinline__ uint32_t f2tf(float f) {
    uint32_t r;
    asm("cvt.rna.tf32.f32 %0, %1;" : "=r"(r) : "f"(f));
    return r;
}
__device__ __forceinline__ void mma8(float c[4], const uint32_t a[4], uint32_t b0, uint32_t b1) {
    asm volatile(
        "mma.sync.aligned.m16n8k8.row.col.f32.tf32.tf32.f32 "
        "{%0,%1,%2,%3}, {%4,%5,%6,%7}, {%8,%9}, {%0,%1,%2,%3};"
        : "+f"(c[0]), "+f"(c[1]), "+f"(c[2]), "+f"(c[3])
        : "r"(a[0]), "r"(a[1]), "r"(a[2]), "r"(a[3]), "r"(b0), "r"(b1));
}

// ---------------- kernel 0: zero accumulators ----------------
__global__ void init_kernel() {
    g_sum = 0.0;
    g_sumsq = 0.0;
}

// ---------------- kernel 1: haversine distance matrix + sum/sumsq ----------------
__global__ void dist_kernel(const float* __restrict__ lat, const float* __restrict__ lon) {
    int i = blockIdx.x;
    float lat_i = lat[i];
    float lon_i = lon[i];
    float cli = __cosf(lat_i);
    double s = 0.0, s2 = 0.0;
    for (int j = threadIdx.x; j < N_TOK; j += 256) {
        float latj = lat[j];
        float dlat = latj - lat_i;
        float dlon = lon[j] - lon_i;
        float sa = __sinf(0.5f * dlat);
        float sb = __sinf(0.5f * dlon);
        float a = sa * sa + cli * __cosf(latj) * (sb * sb);
        a = fminf(fmaxf(a, 0.0f), 1.0f);
        float d = 2.0f * asinf(sqrtf(a));
        g_dist[(size_t)i * N_TOK + j] = d;
        s += (double)d;
        s2 += (double)d * (double)d;
    }
    __shared__ double sh[256];
    __shared__ double sh2[256];
    sh[threadIdx.x] = s;
    sh2[threadIdx.x] = s2;
    __syncthreads();
    for (int off = 128; off > 0; off >>= 1) {
        if (threadIdx.x < off) {
            sh[threadIdx.x] += sh[threadIdx.x + off];
            sh2[threadIdx.x] += sh2[threadIdx.x + off];
        }
        __syncthreads();
    }
    if (threadIdx.x == 0) {
        atomicAdd(&g_sum, sh[0]);
        atomicAdd(&g_sumsq, sh2[0]);
    }
}

// ---------------- kernel 2: finalize std (ddof=1) ----------------
__global__ void finalize_kernel() {
    double M = (double)N_TOK * (double)N_TOK;
    double mean = g_sum / M;
    double var = (g_sumsq - g_sum * mean) / (M - 1.0);
    g_neg_inv_std = (float)(-1.0 / sqrt(var));
}

// ====== 3xTF32 GEMM building blocks (BM=128, BN=64, BK=32, 256 thr) ======
// SMEM word layout: Ah[128*36] | Al[128*36] | Bh[64*36] | Bl[64*36]
#define GA_H 0
#define GA_L (128 * 36)
#define GB_H (2 * 128 * 36)
#define GB_L (2 * 128 * 36 + 64 * 36)
#define GEMM_SMEM_WORDS (2 * 128 * 36 + 2 * 64 * 36)
#define GEMM_SMEM_BYTES (GEMM_SMEM_WORDS * 4)

__device__ __forceinline__ void stage_split_rowf4(uint32_t* hi, uint32_t* lo,
                                                  int word_off, const float4* src) {
    float4 v = *src;
    uint4 h, l;
    h.x = f2tf(v.x); l.x = f2tf(v.x - __uint_as_float(h.x));
    h.y = f2tf(v.y); l.y = f2tf(v.y - __uint_as_float(h.y));
    h.z = f2tf(v.z); l.z = f2tf(v.z - __uint_as_float(h.z));
    h.w = f2tf(v.w); l.w = f2tf(v.w - __uint_as_float(h.w));
    *(uint4*)&hi[word_off] = h;
    *(uint4*)&lo[word_off] = l;
}

// inner compute over one staged BK=32 chunk; acc[8][4] per warp (16x64)
__device__ __forceinline__ void gemm_chunk(const uint32_t* __restrict__ sm,
                                           int w16, int gid, int tig,
                                           float acc[8][4]) {
    const uint32_t* Ah = sm + GA_H;
    const uint32_t* Al = sm + GA_L;
    const uint32_t* Bh = sm + GB_H;
    const uint32_t* Bl = sm + GB_L;
#pragma unroll
    for (int k = 0; k < 4; k++) {
        int k8 = k * 8 + tig;
        uint32_t ah[4], al[4];
        ah[0] = Ah[(w16 + gid) * 36 + k8];
        ah[1] = Ah[(w16 + gid + 8) * 36 + k8];
        ah[2] = Ah[(w16 + gid) * 36 + k8 + 4];
        ah[3] = Ah[(w16 + gid + 8) * 36 + k8 + 4];
        al[0] = Al[(w16 + gid) * 36 + k8];
        al[1] = Al[(w16 + gid + 8) * 36 + k8];
        al[2] = Al[(w16 + gid) * 36 + k8 + 4];
        al[3] = Al[(w16 + gid + 8) * 36 + k8 + 4];
#pragma unroll
        for (int n = 0; n < 8; n++) {
            uint32_t bh0 = Bh[(n * 8 + gid) * 36 + k8];
            uint32_t bh1 = Bh[(n * 8 + gid) * 36 + k8 + 4];
            uint32_t bl0 = Bl[(n * 8 + gid) * 36 + k8];
            uint32_t bl1 = Bl[(n * 8 + gid) * 36 + k8 + 4];
            mma8(acc[n], ah, bh0, bh1);
            mma8(acc[n], al, bh0, bh1);
            mma8(acc[n], ah, bl0, bl1);
        }
    }
}

// ---------------- kernel 3: QKV projection (3xTF32 tensor cores) ----------------
// Grid (1536/64, 4096/128), 256 threads.
__global__ void __launch_bounds__(256, 2) qkv_gemm_tc(const float* __restrict__ X,
                                                      const float* __restrict__ Wq,
                                                      const float* __restrict__ bq) {
    extern __shared__ uint32_t sm[];
    int j0 = blockIdx.x * 64;
    int i0 = blockIdx.y * 128;
    int tid = threadIdx.x;
    int warp = tid >> 5;
    int lane = tid & 31;
    int gid = lane >> 2;
    int tig = lane & 3;
    int w16 = warp * 16;

    float acc[8][4];
#pragma unroll
    for (int n = 0; n < 8; n++)
#pragma unroll
        for (int q = 0; q < 4; q++) acc[n][q] = 0.0f;

    for (int k0 = 0; k0 < C_DIM; k0 += 32) {
        __syncthreads();
        // stage A (X tile 128x32)
#pragma unroll
        for (int i = 0; i < 4; i++) {
            int f4 = tid + i * 256;
            int r = f4 >> 3;
            int c = (f4 & 7) * 4;
            stage_split_rowf4(sm + GA_H, sm + GA_L, r * 36 + c,
                              (const float4*)&X[(size_t)(i0 + r) * C_DIM + k0 + c]);
        }
        // stage B (W tile 64x32)
#pragma unroll
        for (int i = 0; i < 2; i++) {
            int f4 = tid + i * 256;
            int r = f4 >> 3;
            int c = (f4 & 7) * 4;
            stage_split_rowf4(sm + GB_H, sm + GB_L, r * 36 + c,
                              (const float4*)&Wq[(size_t)(j0 + r) * C_DIM + k0 + c]);
        }
        __syncthreads();
        gemm_chunk(sm, w16, gid, tig, acc);
    }

    // epilogue: bias, q-scale, scatter head-major
    int part = j0 / C_DIM;
    int h = (j0 % C_DIM) / DH;
    float* dst = (part == 0) ? g_q : ((part == 1) ? g_k : g_v);
    float sc = (part == 0) ? 0.125f : 1.0f;
    dst += (size_t)h * N_TOK * DH;
#pragma unroll
    for (int n = 0; n < 8; n++) {
        int col = n * 8 + 2 * tig;
        float2 bb = *(const float2*)&bq[j0 + col];
        int r0 = i0 + w16 + gid;
        float2 w0;
        w0.x = (acc[n][0] + bb.x) * sc;
        w0.y = (acc[n][1] + bb.y) * sc;
        *(float2*)&dst[(size_t)r0 * DH + col] = w0;
        float2 w1;
        w1.x = (acc[n][2] + bb.x) * sc;
        w1.y = (acc[n][3] + bb.y) * sc;
        *(float2*)&dst[(size_t)(r0 + 8) * DH + col] = w1;
    }
}

// ---------------- kernel 4: flash attention via mma.sync tf32 ----------------
// Grid (32, 8), 256 threads (8 warps). BM=128 (16 rows/warp), BN=64, dh=64.
#define QS_OFF 0
#define KS_OFF (128 * 68)
#define VS_OFF (KS_OFF + 64 * 68)
#define PS_OFF (VS_OFF + 64 * 68)
#define ATTN_SMEM_WORDS (PS_OFF + 128 * 68)
#define ATTN_SMEM_BYTES (ATTN_SMEM_WORDS * 4)

__global__ void __launch_bounds__(256, 2) attn_mma() {
    extern __shared__ uint32_t sm4[];
    uint32_t* Qs = sm4 + QS_OFF;
    uint32_t* Ks = sm4 + KS_OFF;
    uint32_t* Vs = sm4 + VS_OFF;
    uint32_t* Ps = sm4 + PS_OFF;

    int tid = threadIdx.x;
    int warp = tid >> 5;
    int lane = tid & 31;
    int gid = lane >> 2;
    int tig = lane & 3;
    int w16 = warp * 16;
    int h = blockIdx.y;
    int i0 = blockIdx.x * 128;
    float nis = g_neg_inv_std;

    const float* Q = g_q + (size_t)h * N_TOK * DH;
    const float* K = g_k + (size_t)h * N_TOK * DH;
    const float* V = g_v + (size_t)h * N_TOK * DH;

    {
        int r = tid >> 4;
        int c = (tid & 15) * 4;
#pragma unroll
        for (int p = 0; p < 8; p++) {
            int row = r + p * 16;
            float4 q4 = *(const float4*)&Q[(size_t)(i0 + row) * DH + c];
            uint4 t;
            t.x = f2tf(q4.x); t.y = f2tf(q4.y); t.z = f2tf(q4.z); t.w = f2tf(q4.w);
            *(uint4*)&Qs[row * 68 + c] = t;
        }
    }

    float m0 = -INFINITY, m1 = -INFINITY, l0 = 0.0f, l1 = 0.0f;
    float o[8][4];
#pragma unroll
    for (int n = 0; n < 8; n++)
#pragma unroll
        for (int q = 0; q < 4; q++) o[n][q] = 0.0f;

    const float* d0base = g_dist + (size_t)(i0 + w16 + gid) * N_TOK + 2 * tig;
    const float* d1base = d0base + (size_t)8 * N_TOK;

    for (int kb = 0; kb < N_TOK / 64; kb++) {
        int j0 = kb * 64;
        __syncthreads();
        {
            int r = tid >> 4;
            int c = (tid & 15) * 4;
#pragma unroll
            for (int p = 0; p < 4; p++) {
                int row = r + p * 16;
                float4 k4 = *(const float4*)&K[(size_t)(j0 + row) * DH + c];
                uint4 tk;
                tk.x = f2tf(k4.x); tk.y = f2tf(k4.y); tk.z = f2tf(k4.z); tk.w = f2tf(k4.w);
                *(uint4*)&Ks[row * 68 + c] = tk;
                float4 v4 = *(const float4*)&V[(size_t)(j0 + row) * DH + c];
                uint4 tv;
                tv.x = f2tf(v4.x); tv.y = f2tf(v4.y); tv.z = f2tf(v4.z); tv.w = f2tf(v4.w);
                *(uint4*)&Vs[row * 68 + c] = tv;
            }
        }
        __syncthreads();

        float s[8][4];
#pragma unroll
        for (int n = 0; n < 8; n++)
#pragma unroll
            for (int q = 0; q < 4; q++) s[n][q] = 0.0f;

#pragma unroll
        for (int k = 0; k < 8; k++) {
            uint32_t a[4];
            int k8 = k * 8 + tig;
            a[0] = Qs[(w16 + gid) * 68 + k8];
            a[1] = Qs[(w16 + gid + 8) * 68 + k8];
            a[2] = Qs[(w16 + gid) * 68 + k8 + 4];
            a[3] = Qs[(w16 + gid + 8) * 68 + k8 + 4];
#pragma unroll
            for (int n = 0; n < 8; n++) {
                uint32_t b0 = Ks[(n * 8 + gid) * 68 + k8];
                uint32_t b1 = Ks[(n * 8 + gid) * 68 + k8 + 4];
                mma8(s[n], a, b0, b1);
            }
        }

        float mx0 = -INFINITY, mx1 = -INFINITY;
#pragma unroll
        for (int n = 0; n < 8; n++) {
            float2 b0v = *(const float2*)(d0base + j0 + n * 8);
            float2 b1v = *(const float2*)(d1base + j0 + n * 8);
            s[n][0] += b0v.x * nis;
            s[n][1] += b0v.y * nis;
            s[n][2] += b1v.x * nis;
            s[n][3] += b1v.y * nis;
            mx0 = fmaxf(mx0, fmaxf(s[n][0], s[n][1]));
            mx1 = fmaxf(mx1, fmaxf(s[n][2], s[n][3]));
        }
        mx0 = fmaxf(mx0, __shfl_xor_sync(0xffffffffu, mx0, 1));
        mx0 = fmaxf(mx0, __shfl_xor_sync(0xffffffffu, mx0, 2));
        mx1 = fmaxf(mx1, __shfl_xor_sync(0xffffffffu, mx1, 1));
        mx1 = fmaxf(mx1, __shfl_xor_sync(0xffffffffu, mx1, 2));

        float mn0 = fmaxf(m0, mx0);
        float mn1 = fmaxf(m1, mx1);
        float f0 = __expf(m0 - mn0);
        float f1 = __expf(m1 - mn1);
        m0 = mn0; m1 = mn1;
        l0 *= f0; l1 *= f1;

        float sum0 = 0.0f, sum1 = 0.0f;
#pragma unroll
        for (int n = 0; n < 8; n++) {
            float p00 = __expf(s[n][0] - mn0);
            float p01 = __expf(s[n][1] - mn0);
            float p10 = __expf(s[n][2] - mn1);
            float p11 = __expf(s[n][3] - mn1);
            uint32_t t00 = f2tf(p00), t01 = f2tf(p01);
            uint32_t t10 = f2tf(p10), t11 = f2tf(p11);
            sum0 += __uint_as_float(t00) + __uint_as_float(t01);
            sum1 += __uint_as_float(t10) + __uint_as_float(t11);
            *(uint2*)&Ps[(w16 + gid) * 68 + n * 8 + 2 * tig] = make_uint2(t00, t01);
            *(uint2*)&Ps[(w16 + gid + 8) * 68 + n * 8 + 2 * tig] = make_uint2(t10, t11);
            o[n][0] *= f0; o[n][1] *= f0;
            o[n][2] *= f1; o[n][3] *= f1;
        }
        l0 += sum0;
        l1 += sum1;

        __syncwarp();

#pragma unroll
        for (int k = 0; k < 8; k++) {
            uint32_t a[4];
            int k8 = k * 8 + tig;
            a[0] = Ps[(w16 + gid) * 68 + k8];
            a[1] = Ps[(w16 + gid + 8) * 68 + k8];
            a[2] = Ps[(w16 + gid) * 68 + k8 + 4];
            a[3] = Ps[(w16 + gid + 8) * 68 + k8 + 4];
#pragma unroll
            for (int n = 0; n < 8; n++) {
                uint32_t b0 = Vs[(k * 8 + tig) * 68 + n * 8 + gid];
                uint32_t b1 = Vs[(k * 8 + tig + 4) * 68 + n * 8 + gid];
                mma8(o[n], a, b0, b1);
            }
        }
    }

    l0 += __shfl_xor_sync(0xffffffffu, l0, 1);
    l0 += __shfl_xor_sync(0xffffffffu, l0, 2);
    l1 += __shfl_xor_sync(0xffffffffu, l1, 1);
    l1 += __shfl_xor_sync(0xffffffffu, l1, 2);
    float inv0 = 1.0f / l0;
    float inv1 = 1.0f / l1;

    float* O = g_o + ((size_t)h * N_TOK + i0) * DH;
#pragma unroll
    for (int n = 0; n < 8; n++) {
        float2 w0;
        w0.x = o[n][0] * inv0;
        w0.y = o[n][1] * inv0;
        *(float2*)&O[(size_t)(w16 + gid) * DH + n * 8 + 2 * tig] = w0;
        float2 w1;
        w1.x = o[n][2] * inv1;
        w1.y = o[n][3] * inv1;
        *(float2*)&O[(size_t)(w16 + gid + 8) * DH + n * 8 + 2 * tig] = w1;
    }
}

// ---------------- kernel 5: output projection (3xTF32 tensor cores) ----------------
// Grid (512/64, 4096/128), 256 threads. A gathered from head-major g_o.
__global__ void __launch_bounds__(256, 2) out_gemm_tc(const float* __restrict__ Wo,
                                                      const float* __restrict__ bo,
                                                      float* __restrict__ out) {
    extern __shared__ uint32_t sm[];
    int j0 = blockIdx.x * 64;
    int i0 = blockIdx.y * 128;
    int tid = threadIdx.x;
    int warp = tid >> 5;
    int lane = tid & 31;
    int gid = lane >> 2;
    int tig = lane & 3;
    int w16 = warp * 16;

    float acc[8][4];
#pragma unroll
    for (int n = 0; n < 8; n++)
#pragma unroll
        for (int q = 0; q < 4; q++) acc[n][q] = 0.0f;

    for (int k0 = 0; k0 < C_DIM; k0 += 32) {
        int head = k0 >> 6;
        int kr = k0 & 63;
        const float* Abase = g_o + (size_t)head * N_TOK * DH;
        __syncthreads();
#pragma unroll
        for (int i = 0; i < 4; i++) {
            int f4 = tid + i * 256;
            int r = f4 >> 3;
            int c = (f4 & 7) * 4;
            stage_split_rowf4(sm + GA_H, sm + GA_L, r * 36 + c,
                              (const float4*)&Abase[(size_t)(i0 + r) * DH + kr + c]);
        }
#pragma unroll
        for (int i = 0; i < 2; i++) {
            int f4 = tid + i * 256;
            int r = f4 >> 3;
            int c = (f4 & 7) * 4;
            stage_split_rowf4(sm + GB_H, sm + GB_L, r * 36 + c,
                              (const float4*)&Wo[(size_t)(j0 + r) * C_DIM + k0 + c]);
        }
        __syncthreads();
        gemm_chunk(sm, w16, gid, tig, acc);
    }

#pragma unroll
    for (int n = 0; n < 8; n++) {
        int col = n * 8 + 2 * tig;
        float2 bb = *(const float2*)&bo[j0 + col];
        int r0 = i0 + w16 + gid;
        float2 w0;
        w0.x = acc[n][0] + bb.x;
        w0.y = acc[n][1] + bb.y;
        *(float2*)&out[(size_t)r0 * C_DIM + j0 + col] = w0;
        float2 w1;
        w1.x = acc[n][2] + bb.x;
        w1.y = acc[n][3] + bb.y;
        *(float2*)&out[(size_t)(r0 + 8) * C_DIM + j0 + col] = w1;
    }
}

// ---------------- launch ----------------
extern "C" void kernel_launch(void* const* d_in, const int* in_sizes, int n_in,
                              void* d_out, int out_size) {
    (void)in_sizes; (void)n_in; (void)out_size;
    const float* x     = (const float*)d_in[0];
    const float* lat   = (const float*)d_in[1];
    const float* lon   = (const float*)d_in[2];
    const float* w_qkv = (const float*)d_in[3];
    const float* b_qkv = (const float*)d_in[4];
    const float* w_out = (const float*)d_in[5];
    const float* b_out = (const float*)d_in[6];
    float* out = (float*)d_out;

    init_kernel<<<1, 1>>>();
    dist_kernel<<<N_TOK, 256>>>(lat, lon);
    finalize_kernel<<<1, 1>>>();

    cudaFuncSetAttribute(qkv_gemm_tc, cudaFuncAttributeMaxDynamicSharedMemorySize, GEMM_SMEM_BYTES);
    qkv_gemm_tc<<<dim3(3 * C_DIM / 64, N_TOK / 128), 256, GEMM_SMEM_BYTES>>>(x, w_qkv, b_qkv);

    cudaFuncSetAttribute(attn_mma, cudaFuncAttributeMaxDynamicSharedMemorySize, ATTN_SMEM_BYTES);
    attn_mma<<<dim3(N_TOK / 128, NH), 256, ATTN_SMEM_BYTES>>>();

    cudaFuncSetAttribute(out_gemm_tc, cudaFuncAttributeMaxDynamicSharedMemorySize, GEMM_SMEM_BYTES);
    out_gemm_tc<<<dim3(C_DIM / 64, N_TOK / 128), 256, GEMM_SMEM_BYTES>>>(w_out, b_out, out);
}

// round 8
// speedup vs baseline: 2.5140x; 1.1363x over previous
#include <cuda_runtime.h>
#include <math.h>
#include <stdint.h>

// Problem dims
#define N_TOK 4096
#define C_DIM 512
#define NH 8
#define DH 64

// ---------------- scratch (device globals, no runtime alloc) ----------------
__device__ float  g_dist[(size_t)N_TOK * N_TOK];   // 64 MB haversine distances
__device__ float  g_q[NH * N_TOK * DH];            // head-major [h][n][d], q pre-scaled by 1/8
__device__ float  g_k[NH * N_TOK * DH];
__device__ float  g_v[NH * N_TOK * DH];
__device__ float  g_o[NH * N_TOK * DH];
__device__ double g_sum;
__device__ double g_sumsq;
__device__ float  g_neg_inv_std;

// ---------------- helpers ----------------
__device__ __forceinline__ uint32_t f2tf(float f) {
    uint32_t r;
    asm("cvt.rna.tf32.f32 %0, %1;" : "=r"(r) : "f"(f));
    return r;
}
__device__ __forceinline__ void mma8(float c[4], const uint32_t a[4], uint32_t b0, uint32_t b1) {
    asm volatile(
        "mma.sync.aligned.m16n8k8.row.col.f32.tf32.tf32.f32 "
        "{%0,%1,%2,%3}, {%4,%5,%6,%7}, {%8,%9}, {%0,%1,%2,%3};"
        : "+f"(c[0]), "+f"(c[1]), "+f"(c[2]), "+f"(c[3])
        : "r"(a[0]), "r"(a[1]), "r"(a[2]), "r"(a[3]), "r"(b0), "r"(b1));
}

// ---------------- kernel 0: zero accumulators ----------------
__global__ void init_kernel() {
    g_sum = 0.0;
    g_sumsq = 0.0;
}

// ---------------- kernel 1: haversine distance matrix + sum/sumsq ----------------
__global__ void dist_kernel(const float* __restrict__ lat, const float* __restrict__ lon) {
    int i = blockIdx.x;
    float lat_i = lat[i];
    float lon_i = lon[i];
    float cli = __cosf(lat_i);
    double s = 0.0, s2 = 0.0;
    for (int j = threadIdx.x; j < N_TOK; j += 256) {
        float latj = lat[j];
        float dlat = latj - lat_i;
        float dlon = lon[j] - lon_i;
        float sa = __sinf(0.5f * dlat);
        float sb = __sinf(0.5f * dlon);
        float a = sa * sa + cli * __cosf(latj) * (sb * sb);
        a = fminf(fmaxf(a, 0.0f), 1.0f);
        float d = 2.0f * asinf(sqrtf(a));
        g_dist[(size_t)i * N_TOK + j] = d;
        s += (double)d;
        s2 += (double)d * (double)d;
    }
    __shared__ double sh[256];
    __shared__ double sh2[256];
    sh[threadIdx.x] = s;
    sh2[threadIdx.x] = s2;
    __syncthreads();
    for (int off = 128; off > 0; off >>= 1) {
        if (threadIdx.x < off) {
            sh[threadIdx.x] += sh[threadIdx.x + off];
            sh2[threadIdx.x] += sh2[threadIdx.x + off];
        }
        __syncthreads();
    }
    if (threadIdx.x == 0) {
        atomicAdd(&g_sum, sh[0]);
        atomicAdd(&g_sumsq, sh2[0]);
    }
}

// ---------------- kernel 2: finalize std (ddof=1) ----------------
__global__ void finalize_kernel() {
    double M = (double)N_TOK * (double)N_TOK;
    double mean = g_sum / M;
    double var = (g_sumsq - g_sum * mean) / (M - 1.0);
    g_neg_inv_std = (float)(-1.0 / sqrt(var));
}

// ====== plain-TF32 GEMM building blocks (BM=128, BN=64, BK=32, 256 thr) ======
// SMEM word layout: A[128*36] | B[64*36]
#define GA_OFF 0
#define GB_OFF (128 * 36)
#define GEMM_SMEM_WORDS (128 * 36 + 64 * 36)
#define GEMM_SMEM_BYTES (GEMM_SMEM_WORDS * 4)

__device__ __forceinline__ void stage_tf_rowf4(uint32_t* dst, int word_off, const float4* src) {
    float4 v = *src;
    uint4 h;
    h.x = f2tf(v.x); h.y = f2tf(v.y); h.z = f2tf(v.z); h.w = f2tf(v.w);
    *(uint4*)&dst[word_off] = h;
}

// inner compute over one staged BK=32 chunk; acc[8][4] per warp (16x64)
__device__ __forceinline__ void gemm_chunk(const uint32_t* __restrict__ sm,
                                           int w16, int gid, int tig,
                                           float acc[8][4]) {
    const uint32_t* A = sm + GA_OFF;
    const uint32_t* B = sm + GB_OFF;
#pragma unroll
    for (int k = 0; k < 4; k++) {
        int k8 = k * 8 + tig;
        uint32_t a[4];
        a[0] = A[(w16 + gid) * 36 + k8];
        a[1] = A[(w16 + gid + 8) * 36 + k8];
        a[2] = A[(w16 + gid) * 36 + k8 + 4];
        a[3] = A[(w16 + gid + 8) * 36 + k8 + 4];
#pragma unroll
        for (int n = 0; n < 8; n++) {
            uint32_t b0 = B[(n * 8 + gid) * 36 + k8];
            uint32_t b1 = B[(n * 8 + gid) * 36 + k8 + 4];
            mma8(acc[n], a, b0, b1);
        }
    }
}

// ---------------- kernel 3: QKV projection (tf32 tensor cores) ----------------
// Grid (1536/64, 4096/128), 256 threads.
__global__ void __launch_bounds__(256, 2) qkv_gemm_tc(const float* __restrict__ X,
                                                      const float* __restrict__ Wq,
                                                      const float* __restrict__ bq) {
    extern __shared__ uint32_t sm[];
    int j0 = blockIdx.x * 64;
    int i0 = blockIdx.y * 128;
    int tid = threadIdx.x;
    int warp = tid >> 5;
    int lane = tid & 31;
    int gid = lane >> 2;
    int tig = lane & 3;
    int w16 = warp * 16;

    float acc[8][4];
#pragma unroll
    for (int n = 0; n < 8; n++)
#pragma unroll
        for (int q = 0; q < 4; q++) acc[n][q] = 0.0f;

    for (int k0 = 0; k0 < C_DIM; k0 += 32) {
        __syncthreads();
        // stage A (X tile 128x32)
#pragma unroll
        for (int i = 0; i < 4; i++) {
            int f4 = tid + i * 256;
            int r = f4 >> 3;
            int c = (f4 & 7) * 4;
            stage_tf_rowf4(sm + GA_OFF, r * 36 + c,
                           (const float4*)&X[(size_t)(i0 + r) * C_DIM + k0 + c]);
        }
        // stage B (W tile 64x32)
#pragma unroll
        for (int i = 0; i < 2; i++) {
            int f4 = tid + i * 256;
            int r = f4 >> 3;
            int c = (f4 & 7) * 4;
            stage_tf_rowf4(sm + GB_OFF, r * 36 + c,
                           (const float4*)&Wq[(size_t)(j0 + r) * C_DIM + k0 + c]);
        }
        __syncthreads();
        gemm_chunk(sm, w16, gid, tig, acc);
    }

    // epilogue: bias, q-scale, scatter head-major
    int part = j0 / C_DIM;
    int h = (j0 % C_DIM) / DH;
    float* dst = (part == 0) ? g_q : ((part == 1) ? g_k : g_v);
    float sc = (part == 0) ? 0.125f : 1.0f;
    dst += (size_t)h * N_TOK * DH;
#pragma unroll
    for (int n = 0; n < 8; n++) {
        int col = n * 8 + 2 * tig;
        float2 bb = *(const float2*)&bq[j0 + col];
        int r0 = i0 + w16 + gid;
        float2 w0;
        w0.x = (acc[n][0] + bb.x) * sc;
        w0.y = (acc[n][1] + bb.y) * sc;
        *(float2*)&dst[(size_t)r0 * DH + col] = w0;
        float2 w1;
        w1.x = (acc[n][2] + bb.x) * sc;
        w1.y = (acc[n][3] + bb.y) * sc;
        *(float2*)&dst[(size_t)(r0 + 8) * DH + col] = w1;
    }
}

// ---------------- kernel 4: flash attention via mma.sync tf32 ----------------
// Grid (32, 8), 256 threads (8 warps). BM=128 (16 rows/warp), BN=64, dh=64.
// Register-prefetch pipeline: next tile's K/V fetched during current compute.
#define QS_OFF 0
#define KS_OFF (128 * 68)
#define VS_OFF (KS_OFF + 64 * 68)
#define PS_OFF (VS_OFF + 64 * 68)
#define ATTN_SMEM_WORDS (PS_OFF + 128 * 68)
#define ATTN_SMEM_BYTES (ATTN_SMEM_WORDS * 4)

__global__ void __launch_bounds__(256, 2) attn_mma() {
    extern __shared__ uint32_t sm4[];
    uint32_t* Qs = sm4 + QS_OFF;
    uint32_t* Ks = sm4 + KS_OFF;
    uint32_t* Vs = sm4 + VS_OFF;
    uint32_t* Ps = sm4 + PS_OFF;

    int tid = threadIdx.x;
    int warp = tid >> 5;
    int lane = tid & 31;
    int gid = lane >> 2;
    int tig = lane & 3;
    int w16 = warp * 16;
    int h = blockIdx.y;
    int i0 = blockIdx.x * 128;
    float nis = g_neg_inv_std;

    const float* Q = g_q + (size_t)h * N_TOK * DH;
    const float* K = g_k + (size_t)h * N_TOK * DH;
    const float* V = g_v + (size_t)h * N_TOK * DH;

    // staging coordinates (same for Q/K/V)
    int sr = tid >> 4;             // 0..15
    int sc = (tid & 15) * 4;       // 0..60

    // stage Q tile (128x64 -> tf32 smem, stride 68)
#pragma unroll
    for (int p = 0; p < 8; p++) {
        int row = sr + p * 16;
        float4 q4 = *(const float4*)&Q[(size_t)(i0 + row) * DH + sc];
        uint4 t;
        t.x = f2tf(q4.x); t.y = f2tf(q4.y); t.z = f2tf(q4.z); t.w = f2tf(q4.w);
        *(uint4*)&Qs[row * 68 + sc] = t;
    }

    float m0 = -INFINITY, m1 = -INFINITY, l0 = 0.0f, l1 = 0.0f;
    float o[8][4];
#pragma unroll
    for (int n = 0; n < 8; n++)
#pragma unroll
        for (int q = 0; q < 4; q++) o[n][q] = 0.0f;

    const float* d0base = g_dist + (size_t)(i0 + w16 + gid) * N_TOK + 2 * tig;
    const float* d1base = d0base + (size_t)8 * N_TOK;

    // prefetch tile 0 into registers
    float4 kreg[4], vreg[4];
#pragma unroll
    for (int p = 0; p < 4; p++) {
        int row = sr + p * 16;
        kreg[p] = *(const float4*)&K[(size_t)row * DH + sc];
        vreg[p] = *(const float4*)&V[(size_t)row * DH + sc];
    }

    for (int kb = 0; kb < N_TOK / 64; kb++) {
        int j0 = kb * 64;
        __syncthreads();     // everyone done reading Ks/Vs of previous tile
        // store prefetched K/V (cvt to tf32)
#pragma unroll
        for (int p = 0; p < 4; p++) {
            int row = sr + p * 16;
            uint4 tk;
            tk.x = f2tf(kreg[p].x); tk.y = f2tf(kreg[p].y);
            tk.z = f2tf(kreg[p].z); tk.w = f2tf(kreg[p].w);
            *(uint4*)&Ks[row * 68 + sc] = tk;
            uint4 tv;
            tv.x = f2tf(vreg[p].x); tv.y = f2tf(vreg[p].y);
            tv.z = f2tf(vreg[p].z); tv.w = f2tf(vreg[p].w);
            *(uint4*)&Vs[row * 68 + sc] = tv;
        }
        __syncthreads();

        // issue next tile's loads — latency overlaps all compute below
        if (kb + 1 < N_TOK / 64) {
            int jn = j0 + 64;
#pragma unroll
            for (int p = 0; p < 4; p++) {
                int row = jn + sr + p * 16;
                kreg[p] = *(const float4*)&K[(size_t)row * DH + sc];
                vreg[p] = *(const float4*)&V[(size_t)row * DH + sc];
            }
        }

        // S = Q @ K^T (per warp: 16x64)
        float s[8][4];
#pragma unroll
        for (int n = 0; n < 8; n++)
#pragma unroll
            for (int q = 0; q < 4; q++) s[n][q] = 0.0f;

#pragma unroll
        for (int k = 0; k < 8; k++) {
            uint32_t a[4];
            int k8 = k * 8 + tig;
            a[0] = Qs[(w16 + gid) * 68 + k8];
            a[1] = Qs[(w16 + gid + 8) * 68 + k8];
            a[2] = Qs[(w16 + gid) * 68 + k8 + 4];
            a[3] = Qs[(w16 + gid + 8) * 68 + k8 + 4];
#pragma unroll
            for (int n = 0; n < 8; n++) {
                uint32_t b0 = Ks[(n * 8 + gid) * 68 + k8];
                uint32_t b1 = Ks[(n * 8 + gid) * 68 + k8 + 4];
                mma8(s[n], a, b0, b1);
            }
        }

        // bias + row max
        float mx0 = -INFINITY, mx1 = -INFINITY;
#pragma unroll
        for (int n = 0; n < 8; n++) {
            float2 b0v = *(const float2*)(d0base + j0 + n * 8);
            float2 b1v = *(const float2*)(d1base + j0 + n * 8);
            s[n][0] += b0v.x * nis;
            s[n][1] += b0v.y * nis;
            s[n][2] += b1v.x * nis;
            s[n][3] += b1v.y * nis;
            mx0 = fmaxf(mx0, fmaxf(s[n][0], s[n][1]));
            mx1 = fmaxf(mx1, fmaxf(s[n][2], s[n][3]));
        }
        mx0 = fmaxf(mx0, __shfl_xor_sync(0xffffffffu, mx0, 1));
        mx0 = fmaxf(mx0, __shfl_xor_sync(0xffffffffu, mx0, 2));
        mx1 = fmaxf(mx1, __shfl_xor_sync(0xffffffffu, mx1, 1));
        mx1 = fmaxf(mx1, __shfl_xor_sync(0xffffffffu, mx1, 2));

        float mn0 = fmaxf(m0, mx0);
        float mn1 = fmaxf(m1, mx1);
        float f0 = __expf(m0 - mn0);
        float f1 = __expf(m1 - mn1);
        m0 = mn0; m1 = mn1;
        l0 *= f0; l1 *= f1;

        float sum0 = 0.0f, sum1 = 0.0f;
#pragma unroll
        for (int n = 0; n < 8; n++) {
            float p00 = __expf(s[n][0] - mn0);
            float p01 = __expf(s[n][1] - mn0);
            float p10 = __expf(s[n][2] - mn1);
            float p11 = __expf(s[n][3] - mn1);
            uint32_t t00 = f2tf(p00), t01 = f2tf(p01);
            uint32_t t10 = f2tf(p10), t11 = f2tf(p11);
            sum0 += __uint_as_float(t00) + __uint_as_float(t01);
            sum1 += __uint_as_float(t10) + __uint_as_float(t11);
            *(uint2*)&Ps[(w16 + gid) * 68 + n * 8 + 2 * tig] = make_uint2(t00, t01);
            *(uint2*)&Ps[(w16 + gid + 8) * 68 + n * 8 + 2 * tig] = make_uint2(t10, t11);
            o[n][0] *= f0; o[n][1] *= f0;
            o[n][2] *= f1; o[n][3] *= f1;
        }
        l0 += sum0;
        l1 += sum1;

        __syncwarp();

        // O += P @ V (per warp: 16x64)
#pragma unroll
        for (int k = 0; k < 8; k++) {
            uint32_t a[4];
            int k8 = k * 8 + tig;
            a[0] = Ps[(w16 + gid) * 68 + k8];
            a[1] = Ps[(w16 + gid + 8) * 68 + k8];
            a[2] = Ps[(w16 + gid) * 68 + k8 + 4];
            a[3] = Ps[(w16 + gid + 8) * 68 + k8 + 4];
#pragma unroll
            for (int n = 0; n < 8; n++) {
                uint32_t b0 = Vs[(k * 8 + tig) * 68 + n * 8 + gid];
                uint32_t b1 = Vs[(k * 8 + tig + 4) * 68 + n * 8 + gid];
                mma8(o[n], a, b0, b1);
            }
        }
    }

    l0 += __shfl_xor_sync(0xffffffffu, l0, 1);
    l0 += __shfl_xor_sync(0xffffffffu, l0, 2);
    l1 += __shfl_xor_sync(0xffffffffu, l1, 1);
    l1 += __shfl_xor_sync(0xffffffffu, l1, 2);
    float inv0 = 1.0f / l0;
    float inv1 = 1.0f / l1;

    float* O = g_o + ((size_t)h * N_TOK + i0) * DH;
#pragma unroll
    for (int n = 0; n < 8; n++) {
        float2 w0;
        w0.x = o[n][0] * inv0;
        w0.y = o[n][1] * inv0;
        *(float2*)&O[(size_t)(w16 + gid) * DH + n * 8 + 2 * tig] = w0;
        float2 w1;
        w1.x = o[n][2] * inv1;
        w1.y = o[n][3] * inv1;
        *(float2*)&O[(size_t)(w16 + gid + 8) * DH + n * 8 + 2 * tig] = w1;
    }
}

// ---------------- kernel 5: output projection (tf32 tensor cores) ----------------
// Grid (512/64, 4096/128), 256 threads. A gathered from head-major g_o.
__global__ void __launch_bounds__(256, 2) out_gemm_tc(const float* __restrict__ Wo,
                                                      const float* __restrict__ bo,
                                                      float* __restrict__ out) {
    extern __shared__ uint32_t sm[];
    int j0 = blockIdx.x * 64;
    int i0 = blockIdx.y * 128;
    int tid = threadIdx.x;
    int warp = tid >> 5;
    int lane = tid & 31;
    int gid = lane >> 2;
    int tig = lane & 3;
    int w16 = warp * 16;

    float acc[8][4];
#pragma unroll
    for (int n = 0; n < 8; n++)
#pragma unroll
        for (int q = 0; q < 4; q++) acc[n][q] = 0.0f;

    for (int k0 = 0; k0 < C_DIM; k0 += 32) {
        int head = k0 >> 6;
        int kr = k0 & 63;
        const float* Abase = g_o + (size_t)head * N_TOK * DH;
        __syncthreads();
#pragma unroll
        for (int i = 0; i < 4; i++) {
            int f4 = tid + i * 256;
            int r = f4 >> 3;
            int c = (f4 & 7) * 4;
            stage_tf_rowf4(sm + GA_OFF, r * 36 + c,
                           (const float4*)&Abase[(size_t)(i0 + r) * DH + kr + c]);
        }
#pragma unroll
        for (int i = 0; i < 2; i++) {
            int f4 = tid + i * 256;
            int r = f4 >> 3;
            int c = (f4 & 7) * 4;
            stage_tf_rowf4(sm + GB_OFF, r * 36 + c,
                           (const float4*)&Wo[(size_t)(j0 + r) * C_DIM + k0 + c]);
        }
        __syncthreads();
        gemm_chunk(sm, w16, gid, tig, acc);
    }

#pragma unroll
    for (int n = 0; n < 8; n++) {
        int col = n * 8 + 2 * tig;
        float2 bb = *(const float2*)&bo[j0 + col];
        int r0 = i0 + w16 + gid;
        float2 w0;
        w0.x = acc[n][0] + bb.x;
        w0.y = acc[n][1] + bb.y;
        *(float2*)&out[(size_t)r0 * C_DIM + j0 + col] = w0;
        float2 w1;
        w1.x = acc[n][2] + bb.x;
        w1.y = acc[n][3] + bb.y;
        *(float2*)&out[(size_t)(r0 + 8) * C_DIM + j0 + col] = w1;
    }
}

// ---------------- launch ----------------
extern "C" void kernel_launch(void* const* d_in, const int* in_sizes, int n_in,
                              void* d_out, int out_size) {
    (void)in_sizes; (void)n_in; (void)out_size;
    const float* x     = (const float*)d_in[0];
    const float* lat   = (const float*)d_in[1];
    const float* lon   = (const float*)d_in[2];
    const float* w_qkv = (const float*)d_in[3];
    const float* b_qkv = (const float*)d_in[4];
    const float* w_out = (const float*)d_in[5];
    const float* b_out = (const float*)d_in[6];
    float* out = (float*)d_out;

    init_kernel<<<1, 1>>>();
    dist_kernel<<<N_TOK, 256>>>(lat, lon);
    finalize_kernel<<<1, 1>>>();

    cudaFuncSetAttribute(qkv_gemm_tc, cudaFuncAttributeMaxDynamicSharedMemorySize, GEMM_SMEM_BYTES);
    qkv_gemm_tc<<<dim3(3 * C_DIM / 64, N_TOK / 128), 256, GEMM_SMEM_BYTES>>>(x, w_qkv, b_qkv);

    cudaFuncSetAttribute(attn_mma, cudaFuncAttributeMaxDynamicSharedMemorySize, ATTN_SMEM_BYTES);
    attn_mma<<<dim3(N_TOK / 128, NH), 256, ATTN_SMEM_BYTES>>>();

    cudaFuncSetAttribute(out_gemm_tc, cudaFuncAttributeMaxDynamicSharedMemorySize, GEMM_SMEM_BYTES);
    out_gemm_tc<<<dim3(C_DIM / 64, N_TOK / 128), 256, GEMM_SMEM_BYTES>>>(w_out, b_out, out);
}

// round 10
// speedup vs baseline: 4.0187x; 1.5985x over previous
#include <cuda_runtime.h>
#include <cuda_fp16.h>
#include <math.h>
#include <stdint.h>

// Problem dims
#define N_TOK 4096
#define C_DIM 512
#define NH 8
#define DH 64

// ---------------- scratch (device globals, no runtime alloc) ----------------
__device__ float  g_dist[(size_t)N_TOK * N_TOK];   // 64 MB haversine distances
__device__ __half g_q[NH * N_TOK * DH];            // head-major [h][n][d], q pre-scaled by 1/8
__device__ __half g_k[NH * N_TOK * DH];
__device__ __half g_v[NH * N_TOK * DH];
__device__ float  g_o[NH * N_TOK * DH];
__device__ float4 g_trigA[N_TOK];                  // {sin(lat/2), cos(lat/2), sin(lon/2), cos(lon/2)}
__device__ float  g_clat[N_TOK];                   // cos(lat)
__device__ double g_sum;
__device__ double g_sumsq;
__device__ float  g_neg_inv_std;

// ---------------- helpers ----------------
__device__ __forceinline__ uint32_t f2tf(float f) {
    uint32_t r;
    asm("cvt.rna.tf32.f32 %0, %1;" : "=r"(r) : "f"(f));
    return r;
}
__device__ __forceinline__ void mma8(float c[4], const uint32_t a[4], uint32_t b0, uint32_t b1) {
    asm volatile(
        "mma.sync.aligned.m16n8k8.row.col.f32.tf32.tf32.f32 "
        "{%0,%1,%2,%3}, {%4,%5,%6,%7}, {%8,%9}, {%0,%1,%2,%3};"
        : "+f"(c[0]), "+f"(c[1]), "+f"(c[2]), "+f"(c[3])
        : "r"(a[0]), "r"(a[1]), "r"(a[2]), "r"(a[3]), "r"(b0), "r"(b1));
}
__device__ __forceinline__ void mma16(float c[4], const uint32_t a[4], uint32_t b0, uint32_t b1) {
    asm volatile(
        "mma.sync.aligned.m16n8k16.row.col.f32.f16.f16.f32 "
        "{%0,%1,%2,%3}, {%4,%5,%6,%7}, {%8,%9}, {%0,%1,%2,%3};"
        : "+f"(c[0]), "+f"(c[1]), "+f"(c[2]), "+f"(c[3])
        : "r"(a[0]), "r"(a[1]), "r"(a[2]), "r"(a[3]), "r"(b0), "r"(b1));
}
__device__ __forceinline__ void ldsm4(uint32_t r[4], uint32_t addr) {
    asm volatile("ldmatrix.sync.aligned.m8n8.x4.shared.b16 {%0,%1,%2,%3}, [%4];"
        : "=r"(r[0]), "=r"(r[1]), "=r"(r[2]), "=r"(r[3]) : "r"(addr));
}
__device__ __forceinline__ void ldsm4t(uint32_t r[4], uint32_t addr) {
    asm volatile("ldmatrix.sync.aligned.m8n8.x4.trans.shared.b16 {%0,%1,%2,%3}, [%4];"
        : "=r"(r[0]), "=r"(r[1]), "=r"(r[2]), "=r"(r[3]) : "r"(addr));
}
__device__ __forceinline__ uint32_t smem_u32(const void* p) {
    uint32_t a;
    asm("{ .reg .u64 t; cvta.to.shared.u64 t, %1; cvt.u32.u64 %0, t; }" : "=r"(a) : "l"(p));
    return a;
}
__device__ __forceinline__ void cpa16(uint32_t s, const void* g) {
    asm volatile("cp.async.cg.shared.global [%0], [%1], 16;" :: "r"(s), "l"(g));
}
#define CP_COMMIT() asm volatile("cp.async.commit_group;" ::: "memory")
#define CP_WAIT(n)  asm volatile("cp.async.wait_group %0;" :: "n"(n) : "memory")

__device__ __forceinline__ uint32_t packh2(float a, float b) {
    __half2 h = __floats2half2_rn(a, b);
    return *(uint32_t*)&h;
}

// ---------------- kernel 0: init + trig precompute ----------------
__global__ void init_kernel() {
    g_sum = 0.0;
    g_sumsq = 0.0;
}

__global__ void trig_kernel(const float* __restrict__ lat, const float* __restrict__ lon) {
    int j = blockIdx.x * 256 + threadIdx.x;
    float la = lat[j], lo = lon[j];
    float sh, ch, so, co;
    __sincosf(la * 0.5f, &sh, &ch);
    __sincosf(lo * 0.5f, &so, &co);
    g_trigA[j] = make_float4(sh, ch, so, co);
    g_clat[j] = __cosf(la);
}

// ---------------- kernel 1: haversine distance matrix + sum/sumsq ----------------
__global__ void dist_kernel() {
    int i = blockIdx.x;
    float4 ti = g_trigA[i];
    float cli = g_clat[i];
    double s = 0.0, s2 = 0.0;
    for (int j = threadIdx.x; j < N_TOK; j += 256) {
        float4 tj = g_trigA[j];
        float clj = g_clat[j];
        float sdlat = ti.x * tj.y - ti.y * tj.x;   // sin((lat_i-lat_j)/2)
        float sdlon = ti.z * tj.w - ti.w * tj.z;   // sin((lon_i-lon_j)/2)
        float a = sdlat * sdlat + cli * clj * (sdlon * sdlon);
        a = fminf(fmaxf(a, 0.0f), 1.0f);
        float d = 2.0f * asinf(sqrtf(a));
        g_dist[(size_t)i * N_TOK + j] = d;
        s += (double)d;
        s2 += (double)d * (double)d;
    }
    __shared__ double sh[256];
    __shared__ double sh2[256];
    sh[threadIdx.x] = s;
    sh2[threadIdx.x] = s2;
    __syncthreads();
    for (int off = 128; off > 0; off >>= 1) {
        if (threadIdx.x < off) {
            sh[threadIdx.x] += sh[threadIdx.x + off];
            sh2[threadIdx.x] += sh2[threadIdx.x + off];
        }
        __syncthreads();
    }
    if (threadIdx.x == 0) {
        atomicAdd(&g_sum, sh[0]);
        atomicAdd(&g_sumsq, sh2[0]);
    }
}

// ---------------- kernel 2: finalize std (ddof=1) ----------------
__global__ void finalize_kernel() {
    double M = (double)N_TOK * (double)N_TOK;
    double mean = g_sum / M;
    double var = (g_sumsq - g_sum * mean) / (M - 1.0);
    g_neg_inv_std = (float)(-1.0 / sqrt(var));
}

// ====== plain-TF32 GEMM building blocks (BM=128, BN=64, BK=32, 256 thr) ======
#define GA_OFF 0
#define GB_OFF (128 * 36)
#define GEMM_SMEM_WORDS (128 * 36 + 64 * 36)
#define GEMM_SMEM_BYTES (GEMM_SMEM_WORDS * 4)

__device__ __forceinline__ void stage_tf_rowf4(uint32_t* dst, int word_off, const float4* src) {
    float4 v = *src;
    uint4 h;
    h.x = f2tf(v.x); h.y = f2tf(v.y); h.z = f2tf(v.z); h.w = f2tf(v.w);
    *(uint4*)&dst[word_off] = h;
}

__device__ __forceinline__ void gemm_chunk(const uint32_t* __restrict__ sm,
                                           int w16, int gid, int tig,
                                           float acc[8][4]) {
    const uint32_t* A = sm + GA_OFF;
    const uint32_t* B = sm + GB_OFF;
#pragma unroll
    for (int k = 0; k < 4; k++) {
        int k8 = k * 8 + tig;
        uint32_t a[4];
        a[0] = A[(w16 + gid) * 36 + k8];
        a[1] = A[(w16 + gid + 8) * 36 + k8];
        a[2] = A[(w16 + gid) * 36 + k8 + 4];
        a[3] = A[(w16 + gid + 8) * 36 + k8 + 4];
#pragma unroll
        for (int n = 0; n < 8; n++) {
            uint32_t b0 = B[(n * 8 + gid) * 36 + k8];
            uint32_t b1 = B[(n * 8 + gid) * 36 + k8 + 4];
            mma8(acc[n], a, b0, b1);
        }
    }
}

// ---------------- kernel 3: QKV projection (tf32 tensor cores, fp16 output) ----------------
__global__ void __launch_bounds__(256, 2) qkv_gemm_tc(const float* __restrict__ X,
                                                      const float* __restrict__ Wq,
                                                      const float* __restrict__ bq) {
    extern __shared__ uint32_t sm[];
    int j0 = blockIdx.x * 64;
    int i0 = blockIdx.y * 128;
    int tid = threadIdx.x;
    int warp = tid >> 5;
    int lane = tid & 31;
    int gid = lane >> 2;
    int tig = lane & 3;
    int w16 = warp * 16;

    float acc[8][4];
#pragma unroll
    for (int n = 0; n < 8; n++)
#pragma unroll
        for (int q = 0; q < 4; q++) acc[n][q] = 0.0f;

    for (int k0 = 0; k0 < C_DIM; k0 += 32) {
        __syncthreads();
#pragma unroll
        for (int i = 0; i < 4; i++) {
            int f4 = tid + i * 256;
            int r = f4 >> 3;
            int c = (f4 & 7) * 4;
            stage_tf_rowf4(sm + GA_OFF, r * 36 + c,
                           (const float4*)&X[(size_t)(i0 + r) * C_DIM + k0 + c]);
        }
#pragma unroll
        for (int i = 0; i < 2; i++) {
            int f4 = tid + i * 256;
            int r = f4 >> 3;
            int c = (f4 & 7) * 4;
            stage_tf_rowf4(sm + GB_OFF, r * 36 + c,
                           (const float4*)&Wq[(size_t)(j0 + r) * C_DIM + k0 + c]);
        }
        __syncthreads();
        gemm_chunk(sm, w16, gid, tig, acc);
    }

    // epilogue: bias, q-scale, scatter head-major as fp16
    int part = j0 / C_DIM;
    int h = (j0 % C_DIM) / DH;
    __half* dst = (part == 0) ? g_q : ((part == 1) ? g_k : g_v);
    float sc = (part == 0) ? 0.125f : 1.0f;
    dst += (size_t)h * N_TOK * DH;
#pragma unroll
    for (int n = 0; n < 8; n++) {
        int col = n * 8 + 2 * tig;
        float2 bb = *(const float2*)&bq[j0 + col];
        int r0 = i0 + w16 + gid;
        *(uint32_t*)&dst[(size_t)r0 * DH + col] =
            packh2((acc[n][0] + bb.x) * sc, (acc[n][1] + bb.y) * sc);
        *(uint32_t*)&dst[(size_t)(r0 + 8) * DH + col] =
            packh2((acc[n][2] + bb.x) * sc, (acc[n][3] + bb.y) * sc);
    }
}

// ---------------- kernel 4: flash attention via fp16 mma + ldmatrix + cp.async ----------------
// Grid (32, 8), 256 threads (8 warps). BM=128 (16 rows/warp), BN=64, dh=64.
// SMEM halfs, row stride 72 halfs (144B): Q[128] | K0[64] | V0[64] | K1[64] | V1[64]
#define ROWB 144                       // bytes per row
#define QS_B 0
#define K0_B 18432
#define V0_B (18432 + 9216)
#define K1_B (18432 + 2 * 9216)
#define V1_B (18432 + 3 * 9216)
#define ATTN_SMEM_BYTES (18432 + 4 * 9216)

__global__ void __launch_bounds__(256, 2) attn_mma() {
    extern __shared__ char smem[];
    uint32_t sbase = smem_u32(smem);

    int tid = threadIdx.x;
    int warp = tid >> 5;
    int lane = tid & 31;
    int gid = lane >> 2;
    int tig = lane & 3;
    int w16 = warp * 16;
    int h = blockIdx.y;
    int i0 = blockIdx.x * 128;
    float nis = g_neg_inv_std;

    const __half* Qg = g_q + (size_t)h * N_TOK * DH + (size_t)i0 * DH;
    const __half* Kg = g_k + (size_t)h * N_TOK * DH;
    const __half* Vg = g_v + (size_t)h * N_TOK * DH;

    // ldmatrix lane-address components
    int l15 = lane & 15;
    int lhi = (lane >> 4) * 16;            // byte offset for k/d high half
    int l7 = lane & 7;
    int r16 = (lane & 16) ? 8 : 0;         // row offset for B (S) second tile
    int b8 = (lane & 8) ? 16 : 0;          // byte offset for B (S) k high half

    // ---- prologue: cp.async Q tile + K/V tile 0 ----
#pragma unroll
    for (int t = 0; t < 4; t++) {
        int id = tid + t * 256;            // 0..1023
        int r = id >> 3, c = id & 7;
        cpa16(sbase + QS_B + r * ROWB + c * 16, Qg + r * DH + c * 8);
    }
#pragma unroll
    for (int t = 0; t < 2; t++) {
        int id = tid + t * 256;            // 0..511
        int r = id >> 3, c = id & 7;
        cpa16(sbase + K0_B + r * ROWB + c * 16, Kg + r * DH + c * 8);
        cpa16(sbase + V0_B + r * ROWB + c * 16, Vg + r * DH + c * 8);
    }
    CP_COMMIT();

    float m0 = -INFINITY, m1 = -INFINITY, l0 = 0.0f, l1 = 0.0f;
    float o[8][4];
#pragma unroll
    for (int n = 0; n < 8; n++)
#pragma unroll
        for (int q = 0; q < 4; q++) o[n][q] = 0.0f;

    const float* d0base = g_dist + (size_t)(i0 + w16 + gid) * N_TOK + 2 * tig;
    const float* d1base = d0base + (size_t)8 * N_TOK;

    for (int kb = 0; kb < N_TOK / 64; kb++) {
        int j0 = kb * 64;
        int cur = kb & 1;
        uint32_t Kc = sbase + (cur ? K1_B : K0_B);
        uint32_t Vc = sbase + (cur ? V1_B : V0_B);

        __syncthreads();   // prior reads of the buffer we're about to overwrite are done
        if (kb + 1 < N_TOK / 64) {
            uint32_t Kn = sbase + (cur ? K0_B : K1_B);
            uint32_t Vn = sbase + (cur ? V0_B : V1_B);
            const __half* Kgn = Kg + (size_t)(j0 + 64) * DH;
            const __half* Vgn = Vg + (size_t)(j0 + 64) * DH;
#pragma unroll
            for (int t = 0; t < 2; t++) {
                int id = tid + t * 256;
                int r = id >> 3, c = id & 7;
                cpa16(Kn + r * ROWB + c * 16, Kgn + r * DH + c * 8);
                cpa16(Vn + r * ROWB + c * 16, Vgn + r * DH + c * 8);
            }
            CP_COMMIT();
            CP_WAIT(1);
        } else {
            CP_WAIT(0);
        }
        __syncthreads();

        // ---- S = Q @ K^T : 4 k16-iters × 8 n8-tiles ----
        float s[8][4];
#pragma unroll
        for (int n = 0; n < 8; n++)
#pragma unroll
            for (int q = 0; q < 4; q++) s[n][q] = 0.0f;

#pragma unroll
        for (int k = 0; k < 4; k++) {
            uint32_t a[4];
            ldsm4(a, sbase + QS_B + (w16 + l15) * ROWB + k * 32 + lhi);
#pragma unroll
            for (int np = 0; np < 4; np++) {
                uint32_t b[4];
                ldsm4(b, Kc + (np * 16 + r16 + l7) * ROWB + k * 32 + b8);
                mma16(s[2 * np], a, b[0], b[1]);
                mma16(s[2 * np + 1], a, b[2], b[3]);
            }
        }

        // ---- bias + row max ----
        float mx0 = -INFINITY, mx1 = -INFINITY;
#pragma unroll
        for (int n = 0; n < 8; n++) {
            float2 b0v = *(const float2*)(d0base + j0 + n * 8);
            float2 b1v = *(const float2*)(d1base + j0 + n * 8);
            s[n][0] += b0v.x * nis;
            s[n][1] += b0v.y * nis;
            s[n][2] += b1v.x * nis;
            s[n][3] += b1v.y * nis;
            mx0 = fmaxf(mx0, fmaxf(s[n][0], s[n][1]));
            mx1 = fmaxf(mx1, fmaxf(s[n][2], s[n][3]));
        }
        mx0 = fmaxf(mx0, __shfl_xor_sync(0xffffffffu, mx0, 1));
        mx0 = fmaxf(mx0, __shfl_xor_sync(0xffffffffu, mx0, 2));
        mx1 = fmaxf(mx1, __shfl_xor_sync(0xffffffffu, mx1, 1));
        mx1 = fmaxf(mx1, __shfl_xor_sync(0xffffffffu, mx1, 2));

        float mn0 = fmaxf(m0, mx0);
        float mn1 = fmaxf(m1, mx1);
        float f0 = __expf(m0 - mn0);
        float f1 = __expf(m1 - mn1);
        m0 = mn0; m1 = mn1;
        l0 *= f0; l1 *= f1;

        // ---- exp, accumulate l, rescale O ----
        float sum0 = 0.0f, sum1 = 0.0f;
#pragma unroll
        for (int n = 0; n < 8; n++) {
            s[n][0] = __expf(s[n][0] - mn0);
            s[n][1] = __expf(s[n][1] - mn0);
            s[n][2] = __expf(s[n][2] - mn1);
            s[n][3] = __expf(s[n][3] - mn1);
            sum0 += s[n][0] + s[n][1];
            sum1 += s[n][2] + s[n][3];
            o[n][0] *= f0; o[n][1] *= f0;
            o[n][2] *= f1; o[n][3] *= f1;
        }
        l0 += sum0;
        l1 += sum1;

        // ---- O += P @ V : P stays in registers as A-frags ----
#pragma unroll
        for (int kk = 0; kk < 4; kk++) {
            uint32_t a[4];
            a[0] = packh2(s[2 * kk][0], s[2 * kk][1]);
            a[1] = packh2(s[2 * kk][2], s[2 * kk][3]);
            a[2] = packh2(s[2 * kk + 1][0], s[2 * kk + 1][1]);
            a[3] = packh2(s[2 * kk + 1][2], s[2 * kk + 1][3]);
#pragma unroll
            for (int dp = 0; dp < 4; dp++) {
                uint32_t b[4];
                ldsm4t(b, Vc + (kk * 16 + l15) * ROWB + dp * 32 + lhi);
                mma16(o[2 * dp], a, b[0], b[1]);
                mma16(o[2 * dp + 1], a, b[2], b[3]);
            }
        }
    }

    l0 += __shfl_xor_sync(0xffffffffu, l0, 1);
    l0 += __shfl_xor_sync(0xffffffffu, l0, 2);
    l1 += __shfl_xor_sync(0xffffffffu, l1, 1);
    l1 += __shfl_xor_sync(0xffffffffu, l1, 2);
    float inv0 = 1.0f / l0;
    float inv1 = 1.0f / l1;

    float* O = g_o + ((size_t)h * N_TOK + i0) * DH;
#pragma unroll
    for (int n = 0; n < 8; n++) {
        float2 w0;
        w0.x = o[n][0] * inv0;
        w0.y = o[n][1] * inv0;
        *(float2*)&O[(size_t)(w16 + gid) * DH + n * 8 + 2 * tig] = w0;
        float2 w1;
        w1.x = o[n][2] * inv1;
        w1.y = o[n][3] * inv1;
        *(float2*)&O[(size_t)(w16 + gid + 8) * DH + n * 8 + 2 * tig] = w1;
    }
}

// ---------------- kernel 5: output projection (tf32 tensor cores) ----------------
__global__ void __launch_bounds__(256, 2) out_gemm_tc(const float* __restrict__ Wo,
                                                      const float* __restrict__ bo,
                                                      float* __restrict__ out) {
    extern __shared__ uint32_t sm[];
    int j0 = blockIdx.x * 64;
    int i0 = blockIdx.y * 128;
    int tid = threadIdx.x;
    int warp = tid >> 5;
    int lane = tid & 31;
    int gid = lane >> 2;
    int tig = lane & 3;
    int w16 = warp * 16;

    float acc[8][4];
#pragma unroll
    for (int n = 0; n < 8; n++)
#pragma unroll
        for (int q = 0; q < 4; q++) acc[n][q] = 0.0f;

    for (int k0 = 0; k0 < C_DIM; k0 += 32) {
        int head = k0 >> 6;
        int kr = k0 & 63;
        const float* Abase = g_o + (size_t)head * N_TOK * DH;
        __syncthreads();
#pragma unroll
        for (int i = 0; i < 4; i++) {
            int f4 = tid + i * 256;
            int r = f4 >> 3;
            int c = (f4 & 7) * 4;
            stage_tf_rowf4(sm + GA_OFF, r * 36 + c,
                           (const float4*)&Abase[(size_t)(i0 + r) * DH + kr + c]);
        }
#pragma unroll
        for (int i = 0; i < 2; i++) {
            int f4 = tid + i * 256;
            int r = f4 >> 3;
            int c = (f4 & 7) * 4;
            stage_tf_rowf4(sm + GB_OFF, r * 36 + c,
                           (const float4*)&Wo[(size_t)(j0 + r) * C_DIM + k0 + c]);
        }
        __syncthreads();
        gemm_chunk(sm, w16, gid, tig, acc);
    }

#pragma unroll
    for (int n = 0; n < 8; n++) {
        int col = n * 8 + 2 * tig;
        float2 bb = *(const float2*)&bo[j0 + col];
        int r0 = i0 + w16 + gid;
        float2 w0;
        w0.x = acc[n][0] + bb.x;
        w0.y = acc[n][1] + bb.y;
        *(float2*)&out[(size_t)r0 * C_DIM + j0 + col] = w0;
        float2 w1;
        w1.x = acc[n][2] + bb.x;
        w1.y = acc[n][3] + bb.y;
        *(float2*)&out[(size_t)(r0 + 8) * C_DIM + j0 + col] = w1;
    }
}

// ---------------- launch ----------------
extern "C" void kernel_launch(void* const* d_in, const int* in_sizes, int n_in,
                              void* d_out, int out_size) {
    (void)in_sizes; (void)n_in; (void)out_size;
    const float* x     = (const float*)d_in[0];
    const float* lat   = (const float*)d_in[1];
    const float* lon   = (const float*)d_in[2];
    const float* w_qkv = (const float*)d_in[3];
    const float* b_qkv = (const float*)d_in[4];
    const float* w_out = (const float*)d_in[5];
    const float* b_out = (const float*)d_in[6];
    float* out = (float*)d_out;

    init_kernel<<<1, 1>>>();
    trig_kernel<<<N_TOK / 256, 256>>>(lat, lon);
    dist_kernel<<<N_TOK, 256>>>();
    finalize_kernel<<<1, 1>>>();

    cudaFuncSetAttribute(qkv_gemm_tc, cudaFuncAttributeMaxDynamicSharedMemorySize, GEMM_SMEM_BYTES);
    qkv_gemm_tc<<<dim3(3 * C_DIM / 64, N_TOK / 128), 256, GEMM_SMEM_BYTES>>>(x, w_qkv, b_qkv);

    cudaFuncSetAttribute(attn_mma, cudaFuncAttributeMaxDynamicSharedMemorySize, ATTN_SMEM_BYTES);
    attn_mma<<<dim3(N_TOK / 128, NH), 256, ATTN_SMEM_BYTES>>>();

    cudaFuncSetAttribute(out_gemm_tc, cudaFuncAttributeMaxDynamicSharedMemorySize, GEMM_SMEM_BYTES);
    out_gemm_tc<<<dim3(C_DIM / 64, N_TOK / 128), 256, GEMM_SMEM_BYTES>>>(w_out, b_out, out);
}

// round 12
// speedup vs baseline: 4.5305x; 1.1273x over previous
#include <cuda_runtime.h>
#include <cuda_fp16.h>
#include <math.h>
#include <stdint.h>

// Problem dims
#define N_TOK 4096
#define C_DIM 512
#define NH 8
#define DH 64
#define L2E 1.44269504f

// ---------------- scratch (device globals, no runtime alloc) ----------------
__device__ float  g_dist[(size_t)N_TOK * N_TOK];   // 64 MB haversine distances
__device__ __half g_xh[N_TOK * C_DIM];             // X in fp16
__device__ __half g_wqh[3 * C_DIM * C_DIM];        // w_qkv in fp16
__device__ __half g_woh[C_DIM * C_DIM];            // w_out in fp16
__device__ __half g_q[NH * N_TOK * DH];            // head-major [h][n][d], q scaled by L2E/8
__device__ __half g_k[NH * N_TOK * DH];
__device__ __half g_v[NH * N_TOK * DH];
__device__ __half g_o[NH * N_TOK * DH];            // attention output (fp16)
__device__ float4 g_trigA[N_TOK];                  // {sin(lat/2), cos(lat/2), sin(lon/2), cos(lon/2)}
__device__ float  g_clat[N_TOK];                   // cos(lat)
__device__ double g_sum;
__device__ double g_sumsq;
__device__ float  g_neg_inv_std;                   // includes L2E factor

// ---------------- helpers ----------------
__device__ __forceinline__ void mma16(float c[4], const uint32_t a[4], uint32_t b0, uint32_t b1) {
    asm volatile(
        "mma.sync.aligned.m16n8k16.row.col.f32.f16.f16.f32 "
        "{%0,%1,%2,%3}, {%4,%5,%6,%7}, {%8,%9}, {%0,%1,%2,%3};"
        : "+f"(c[0]), "+f"(c[1]), "+f"(c[2]), "+f"(c[3])
        : "r"(a[0]), "r"(a[1]), "r"(a[2]), "r"(a[3]), "r"(b0), "r"(b1));
}
__device__ __forceinline__ void ldsm4(uint32_t r[4], uint32_t addr) {
    asm volatile("ldmatrix.sync.aligned.m8n8.x4.shared.b16 {%0,%1,%2,%3}, [%4];"
        : "=r"(r[0]), "=r"(r[1]), "=r"(r[2]), "=r"(r[3]) : "r"(addr));
}
__device__ __forceinline__ void ldsm4t(uint32_t r[4], uint32_t addr) {
    asm volatile("ldmatrix.sync.aligned.m8n8.x4.trans.shared.b16 {%0,%1,%2,%3}, [%4];"
        : "=r"(r[0]), "=r"(r[1]), "=r"(r[2]), "=r"(r[3]) : "r"(addr));
}
__device__ __forceinline__ uint32_t smem_u32(const void* p) {
    uint32_t a;
    asm("{ .reg .u64 t; cvta.to.shared.u64 t, %1; cvt.u32.u64 %0, t; }" : "=r"(a) : "l"(p));
    return a;
}
__device__ __forceinline__ void cpa16(uint32_t s, const void* g) {
    asm volatile("cp.async.cg.shared.global [%0], [%1], 16;" :: "r"(s), "l"(g));
}
#define CP_COMMIT() asm volatile("cp.async.commit_group;" ::: "memory")
#define CP_WAIT(n)  asm volatile("cp.async.wait_group %0;" :: "n"(n) : "memory")

__device__ __forceinline__ uint32_t packh2(float a, float b) {
    __half2 h = __floats2half2_rn(a, b);
    return *(uint32_t*)&h;
}
__device__ __forceinline__ float ex2(float x) {
    float y;
    asm("ex2.approx.ftz.f32 %0, %1;" : "=f"(y) : "f"(x));
    return y;
}

// ---------------- kernel 0: init ----------------
__global__ void init_kernel() {
    g_sum = 0.0;
    g_sumsq = 0.0;
}

// ---------------- kernel 0b: fp16 conversion of X, w_qkv, w_out ----------------
// float4-granular: X 524288 | wqkv 196608 | wout 65536  (total 786432 float4)
__global__ void cvt_kernel(const float* __restrict__ x,
                           const float* __restrict__ wq,
                           const float* __restrict__ wo) {
    int idx = blockIdx.x * 256 + threadIdx.x;
    const float4* src;
    uint2* dst;
    if (idx < 524288) {
        src = (const float4*)x + idx;
        dst = (uint2*)g_xh + idx;
    } else if (idx < 524288 + 196608) {
        src = (const float4*)wq + (idx - 524288);
        dst = (uint2*)g_wqh + (idx - 524288);
    } else {
        src = (const float4*)wo + (idx - 720896);
        dst = (uint2*)g_woh + (idx - 720896);
    }
    float4 v = *src;
    uint2 o;
    o.x = packh2(v.x, v.y);
    o.y = packh2(v.z, v.w);
    *dst = o;
}

// ---------------- kernel 0c: trig precompute ----------------
__global__ void trig_kernel(const float* __restrict__ lat, const float* __restrict__ lon) {
    int j = blockIdx.x * 256 + threadIdx.x;
    float la = lat[j], lo = lon[j];
    float sh, ch, so, co;
    __sincosf(la * 0.5f, &sh, &ch);
    __sincosf(lo * 0.5f, &so, &co);
    g_trigA[j] = make_float4(sh, ch, so, co);
    g_clat[j] = __cosf(la);
}

// ---------------- kernel 1: haversine distance matrix + sum/sumsq ----------------
__global__ void dist_kernel() {
    int i = blockIdx.x;
    float4 ti = g_trigA[i];
    float cli = g_clat[i];
    double s = 0.0, s2 = 0.0;
    for (int j = threadIdx.x; j < N_TOK; j += 256) {
        float4 tj = g_trigA[j];
        float clj = g_clat[j];
        float sdlat = ti.x * tj.y - ti.y * tj.x;
        float sdlon = ti.z * tj.w - ti.w * tj.z;
        float a = sdlat * sdlat + cli * clj * (sdlon * sdlon);
        a = fminf(fmaxf(a, 0.0f), 1.0f);
        float d = 2.0f * asinf(sqrtf(a));
        g_dist[(size_t)i * N_TOK + j] = d;
        s += (double)d;
        s2 += (double)d * (double)d;
    }
    __shared__ double sh[256];
    __shared__ double sh2[256];
    sh[threadIdx.x] = s;
    sh2[threadIdx.x] = s2;
    __syncthreads();
    for (int off = 128; off > 0; off >>= 1) {
        if (threadIdx.x < off) {
            sh[threadIdx.x] += sh[threadIdx.x + off];
            sh2[threadIdx.x] += sh2[threadIdx.x + off];
        }
        __syncthreads();
    }
    if (threadIdx.x == 0) {
        atomicAdd(&g_sum, sh[0]);
        atomicAdd(&g_sumsq, sh2[0]);
    }
}

// ---------------- kernel 2: finalize std (ddof=1), fold log2e ----------------
__global__ void finalize_kernel() {
    double M = (double)N_TOK * (double)N_TOK;
    double mean = g_sum / M;
    double var = (g_sumsq - g_sum * mean) / (M - 1.0);
    g_neg_inv_std = (float)(-(double)L2E / sqrt(var));
}

// ====== fp16 GEMM tile geometry (shared by qkv/out projections) ======
// BM=128, BN=64, BK=64, 256 threads, double-buffered cp.async.
#define ROWB 144
#define PA0_B 0
#define PA1_B 18432
#define PB0_B 36864
#define PB1_B 46080
#define PROJ_SMEM_BYTES 55296

// ---------------- kernel 3: QKV projection (fp16 mma) ----------------
// Grid (1536/64, 4096/128), 256 threads.
__global__ void __launch_bounds__(256, 2) qkv_gemm_h(const float* __restrict__ bq) {
    extern __shared__ char smem[];
    uint32_t sbase = smem_u32(smem);
    int j0 = blockIdx.x * 64;
    int i0 = blockIdx.y * 128;
    int tid = threadIdx.x;
    int warp = tid >> 5;
    int lane = tid & 31;
    int gid = lane >> 2;
    int tig = lane & 3;
    int w16 = warp * 16;
    int l15 = lane & 15;
    int lhi = (lane >> 4) * 16;
    int l7 = lane & 7;
    int r16 = (lane & 16) ? 8 : 0;
    int b8 = (lane & 8) ? 16 : 0;

    const __half* Ag = g_xh + (size_t)i0 * C_DIM;
    const __half* Bg = g_wqh + (size_t)j0 * C_DIM;

    // prologue: chunk 0
#pragma unroll
    for (int t = 0; t < 4; t++) {
        int id = tid + t * 256;
        int r = id >> 3, c = id & 7;
        cpa16(sbase + PA0_B + r * ROWB + c * 16, Ag + (size_t)r * C_DIM + c * 8);
    }
#pragma unroll
    for (int t = 0; t < 2; t++) {
        int id = tid + t * 256;
        int r = id >> 3, c = id & 7;
        cpa16(sbase + PB0_B + r * ROWB + c * 16, Bg + (size_t)r * C_DIM + c * 8);
    }
    CP_COMMIT();

    float acc[8][4];
#pragma unroll
    for (int n = 0; n < 8; n++)
#pragma unroll
        for (int q = 0; q < 4; q++) acc[n][q] = 0.0f;

    for (int kc = 0; kc < 8; kc++) {
        int cur = kc & 1;
        uint32_t Ac = sbase + (cur ? PA1_B : PA0_B);
        uint32_t Bc = sbase + (cur ? PB1_B : PB0_B);
        __syncthreads();
        if (kc + 1 < 8) {
            uint32_t An = sbase + (cur ? PA0_B : PA1_B);
            uint32_t Bn = sbase + (cur ? PB0_B : PB1_B);
            int ko = (kc + 1) * 64;
#pragma unroll
            for (int t = 0; t < 4; t++) {
                int id = tid + t * 256;
                int r = id >> 3, c = id & 7;
                cpa16(An + r * ROWB + c * 16, Ag + (size_t)r * C_DIM + ko + c * 8);
            }
#pragma unroll
            for (int t = 0; t < 2; t++) {
                int id = tid + t * 256;
                int r = id >> 3, c = id & 7;
                cpa16(Bn + r * ROWB + c * 16, Bg + (size_t)r * C_DIM + ko + c * 8);
            }
            CP_COMMIT();
            CP_WAIT(1);
        } else {
            CP_WAIT(0);
        }
        __syncthreads();

#pragma unroll
        for (int k = 0; k < 4; k++) {
            uint32_t a[4];
            ldsm4(a, Ac + (w16 + l15) * ROWB + k * 32 + lhi);
#pragma unroll
            for (int np = 0; np < 4; np++) {
                uint32_t b[4];
                ldsm4(b, Bc + (np * 16 + r16 + l7) * ROWB + k * 32 + b8);
                mma16(acc[2 * np], a, b[0], b[1]);
                mma16(acc[2 * np + 1], a, b[2], b[3]);
            }
        }
    }

    // epilogue: bias, q-scale (1/8 * log2e), scatter head-major fp16
    int part = j0 / C_DIM;
    int h = (j0 % C_DIM) / DH;
    __half* dst = (part == 0) ? g_q : ((part == 1) ? g_k : g_v);
    float sc = (part == 0) ? (0.125f * L2E) : 1.0f;
    dst += (size_t)h * N_TOK * DH;
#pragma unroll
    for (int n = 0; n < 8; n++) {
        int col = n * 8 + 2 * tig;
        float2 bb = *(const float2*)&bq[j0 + col];
        int r0 = i0 + w16 + gid;
        *(uint32_t*)&dst[(size_t)r0 * DH + col] =
            packh2((acc[n][0] + bb.x) * sc, (acc[n][1] + bb.y) * sc);
        *(uint32_t*)&dst[(size_t)(r0 + 8) * DH + col] =
            packh2((acc[n][2] + bb.x) * sc, (acc[n][3] + bb.y) * sc);
    }
}

// ---------------- kernel 4: flash attention (fp16 mma, exp2 domain) ----------------
// Grid (32, 8), 256 threads. BM=128, BN=64, dh=64.
#define QS_B 0
#define K0_B 18432
#define V0_B (18432 + 9216)
#define K1_B (18432 + 2 * 9216)
#define V1_B (18432 + 3 * 9216)
#define ATTN_SMEM_BYTES (18432 + 4 * 9216)

__global__ void __launch_bounds__(256, 2) attn_mma() {
    extern __shared__ char smem[];
    uint32_t sbase = smem_u32(smem);

    int tid = threadIdx.x;
    int warp = tid >> 5;
    int lane = tid & 31;
    int gid = lane >> 2;
    int tig = lane & 3;
    int w16 = warp * 16;
    int h = blockIdx.y;
    int i0 = blockIdx.x * 128;
    float nis = g_neg_inv_std;     // -(log2e)/std

    const __half* Qg = g_q + (size_t)h * N_TOK * DH + (size_t)i0 * DH;
    const __half* Kg = g_k + (size_t)h * N_TOK * DH;
    const __half* Vg = g_v + (size_t)h * N_TOK * DH;

    int l15 = lane & 15;
    int lhi = (lane >> 4) * 16;
    int l7 = lane & 7;
    int r16 = (lane & 16) ? 8 : 0;
    int b8 = (lane & 8) ? 16 : 0;

    // prologue: Q + K/V tile 0
#pragma unroll
    for (int t = 0; t < 4; t++) {
        int id = tid + t * 256;
        int r = id >> 3, c = id & 7;
        cpa16(sbase + QS_B + r * ROWB + c * 16, Qg + r * DH + c * 8);
    }
#pragma unroll
    for (int t = 0; t < 2; t++) {
        int id = tid + t * 256;
        int r = id >> 3, c = id & 7;
        cpa16(sbase + K0_B + r * ROWB + c * 16, Kg + r * DH + c * 8);
        cpa16(sbase + V0_B + r * ROWB + c * 16, Vg + r * DH + c * 8);
    }
    CP_COMMIT();

    float m0 = -INFINITY, m1 = -INFINITY, l0 = 0.0f, l1 = 0.0f;
    float o[8][4];
#pragma unroll
    for (int n = 0; n < 8; n++)
#pragma unroll
        for (int q = 0; q < 4; q++) o[n][q] = 0.0f;

    const float* d0base = g_dist + (size_t)(i0 + w16 + gid) * N_TOK + 2 * tig;
    const float* d1base = d0base + (size_t)8 * N_TOK;

    for (int kb = 0; kb < N_TOK / 64; kb++) {
        int j0 = kb * 64;
        int cur = kb & 1;
        uint32_t Kc = sbase + (cur ? K1_B : K0_B);
        uint32_t Vc = sbase + (cur ? V1_B : V0_B);

        // issue bias loads FIRST — latency covered by staging + S-MMA below
        float2 bx0[8], bx1[8];
#pragma unroll
        for (int n = 0; n < 8; n++) {
            bx0[n] = *(const float2*)(d0base + j0 + n * 8);
            bx1[n] = *(const float2*)(d1base + j0 + n * 8);
        }

        __syncthreads();
        if (kb + 1 < N_TOK / 64) {
            uint32_t Kn = sbase + (cur ? K0_B : K1_B);
            uint32_t Vn = sbase + (cur ? V0_B : V1_B);
            const __half* Kgn = Kg + (size_t)(j0 + 64) * DH;
            const __half* Vgn = Vg + (size_t)(j0 + 64) * DH;
#pragma unroll
            for (int t = 0; t < 2; t++) {
                int id = tid + t * 256;
                int r = id >> 3, c = id & 7;
                cpa16(Kn + r * ROWB + c * 16, Kgn + r * DH + c * 8);
                cpa16(Vn + r * ROWB + c * 16, Vgn + r * DH + c * 8);
            }
            CP_COMMIT();
            CP_WAIT(1);
        } else {
            CP_WAIT(0);
        }
        __syncthreads();

        // S = Q @ K^T
        float s[8][4];
#pragma unroll
        for (int n = 0; n < 8; n++)
#pragma unroll
            for (int q = 0; q < 4; q++) s[n][q] = 0.0f;

#pragma unroll
        for (int k = 0; k < 4; k++) {
            uint32_t a[4];
            ldsm4(a, sbase + QS_B + (w16 + l15) * ROWB + k * 32 + lhi);
#pragma unroll
            for (int np = 0; np < 4; np++) {
                uint32_t b[4];
                ldsm4(b, Kc + (np * 16 + r16 + l7) * ROWB + k * 32 + b8);
                mma16(s[2 * np], a, b[0], b[1]);
                mma16(s[2 * np + 1], a, b[2], b[3]);
            }
        }

        // bias + row max (log2 domain)
        float mx0 = -INFINITY, mx1 = -INFINITY;
#pragma unroll
        for (int n = 0; n < 8; n++) {
            s[n][0] += bx0[n].x * nis;
            s[n][1] += bx0[n].y * nis;
            s[n][2] += bx1[n].x * nis;
            s[n][3] += bx1[n].y * nis;
            mx0 = fmaxf(mx0, fmaxf(s[n][0], s[n][1]));
            mx1 = fmaxf(mx1, fmaxf(s[n][2], s[n][3]));
        }
        mx0 = fmaxf(mx0, __shfl_xor_sync(0xffffffffu, mx0, 1));
        mx0 = fmaxf(mx0, __shfl_xor_sync(0xffffffffu, mx0, 2));
        mx1 = fmaxf(mx1, __shfl_xor_sync(0xffffffffu, mx1, 1));
        mx1 = fmaxf(mx1, __shfl_xor_sync(0xffffffffu, mx1, 2));

        float mn0 = fmaxf(m0, mx0);
        float mn1 = fmaxf(m1, mx1);
        float f0 = ex2(m0 - mn0);
        float f1 = ex2(m1 - mn1);
        m0 = mn0; m1 = mn1;
        l0 *= f0; l1 *= f1;

        float sum0 = 0.0f, sum1 = 0.0f;
#pragma unroll
        for (int n = 0; n < 8; n++) {
            s[n][0] = ex2(s[n][0] - mn0);
            s[n][1] = ex2(s[n][1] - mn0);
            s[n][2] = ex2(s[n][2] - mn1);
            s[n][3] = ex2(s[n][3] - mn1);
            sum0 += s[n][0] + s[n][1];
            sum1 += s[n][2] + s[n][3];
            o[n][0] *= f0; o[n][1] *= f0;
            o[n][2] *= f1; o[n][3] *= f1;
        }
        l0 += sum0;
        l1 += sum1;

        // O += P @ V, P in registers
#pragma unroll
        for (int kk = 0; kk < 4; kk++) {
            uint32_t a[4];
            a[0] = packh2(s[2 * kk][0], s[2 * kk][1]);
            a[1] = packh2(s[2 * kk][2], s[2 * kk][3]);
            a[2] = packh2(s[2 * kk + 1][0], s[2 * kk + 1][1]);
            a[3] = packh2(s[2 * kk + 1][2], s[2 * kk + 1][3]);
#pragma unroll
            for (int dp = 0; dp < 4; dp++) {
                uint32_t b[4];
                ldsm4t(b, Vc + (kk * 16 + l15) * ROWB + dp * 32 + lhi);
                mma16(o[2 * dp], a, b[0], b[1]);
                mma16(o[2 * dp + 1], a, b[2], b[3]);
            }
        }
    }

    l0 += __shfl_xor_sync(0xffffffffu, l0, 1);
    l0 += __shfl_xor_sync(0xffffffffu, l0, 2);
    l1 += __shfl_xor_sync(0xffffffffu, l1, 1);
    l1 += __shfl_xor_sync(0xffffffffu, l1, 2);
    float inv0 = 1.0f / l0;
    float inv1 = 1.0f / l1;

    __half* O = g_o + ((size_t)h * N_TOK + i0) * DH;
#pragma unroll
    for (int n = 0; n < 8; n++) {
        int col = n * 8 + 2 * tig;
        *(uint32_t*)&O[(size_t)(w16 + gid) * DH + col] = packh2(o[n][0] * inv0, o[n][1] * inv0);
        *(uint32_t*)&O[(size_t)(w16 + gid + 8) * DH + col] = packh2(o[n][2] * inv1, o[n][3] * inv1);
    }
}

// ---------------- kernel 5: output projection (fp16 mma) ----------------
// Grid (512/64, 4096/128), 256 threads. A = g_o head-major fp16, chunk k = head.
__global__ void __launch_bounds__(256, 2) out_gemm_h(const float* __restrict__ bo,
                                                     float* __restrict__ out) {
    extern __shared__ char smem[];
    uint32_t sbase = smem_u32(smem);
    int j0 = blockIdx.x * 64;
    int i0 = blockIdx.y * 128;
    int tid = threadIdx.x;
    int warp = tid >> 5;
    int lane = tid & 31;
    int gid = lane >> 2;
    int tig = lane & 3;
    int w16 = warp * 16;
    int l15 = lane & 15;
    int lhi = (lane >> 4) * 16;
    int l7 = lane & 7;
    int r16 = (lane & 16) ? 8 : 0;
    int b8 = (lane & 8) ? 16 : 0;

    // prologue: head 0 chunk
#pragma unroll
    for (int t = 0; t < 4; t++) {
        int id = tid + t * 256;
        int r = id >> 3, c = id & 7;
        cpa16(sbase + PA0_B + r * ROWB + c * 16, g_o + (size_t)(i0 + r) * DH + c * 8);
    }
#pragma unroll
    for (int t = 0; t < 2; t++) {
        int id = tid + t * 256;
        int r = id >> 3, c = id & 7;
        cpa16(sbase + PB0_B + r * ROWB + c * 16, g_woh + (size_t)(j0 + r) * C_DIM + c * 8);
    }
    CP_COMMIT();

    float acc[8][4];
#pragma unroll
    for (int n = 0; n < 8; n++)
#pragma unroll
        for (int q = 0; q < 4; q++) acc[n][q] = 0.0f;

    for (int kc = 0; kc < 8; kc++) {
        int cur = kc & 1;
        uint32_t Ac = sbase + (cur ? PA1_B : PA0_B);
        uint32_t Bc = sbase + (cur ? PB1_B : PB0_B);
        __syncthreads();
        if (kc + 1 < 8) {
            uint32_t An = sbase + (cur ? PA0_B : PA1_B);
            uint32_t Bn = sbase + (cur ? PB0_B : PB1_B);
            int hn = kc + 1;
            const __half* Agn = g_o + (size_t)hn * N_TOK * DH + (size_t)i0 * DH;
            const __half* Bgn = g_woh + (size_t)j0 * C_DIM + hn * DH;
#pragma unroll
            for (int t = 0; t < 4; t++) {
                int id = tid + t * 256;
                int r = id >> 3, c = id & 7;
                cpa16(An + r * ROWB + c * 16, Agn + (size_t)r * DH + c * 8);
            }
#pragma unroll
            for (int t = 0; t < 2; t++) {
                int id = tid + t * 256;
                int r = id >> 3, c = id & 7;
                cpa16(Bn + r * ROWB + c * 16, Bgn + (size_t)r * C_DIM + c * 8);
            }
            CP_COMMIT();
            CP_WAIT(1);
        } else {
            CP_WAIT(0);
        }
        __syncthreads();

#pragma unroll
        for (int k = 0; k < 4; k++) {
            uint32_t a[4];
            ldsm4(a, Ac + (w16 + l15) * ROWB + k * 32 + lhi);
#pragma unroll
            for (int np = 0; np < 4; np++) {
                uint32_t b[4];
                ldsm4(b, Bc + (np * 16 + r16 + l7) * ROWB + k * 32 + b8);
                mma16(acc[2 * np], a, b[0], b[1]);
                mma16(acc[2 * np + 1], a, b[2], b[3]);
            }
        }
    }

#pragma unroll
    for (int n = 0; n < 8; n++) {
        int col = n * 8 + 2 * tig;
        float2 bb = *(const float2*)&bo[j0 + col];
        int r0 = i0 + w16 + gid;
        float2 w0;
        w0.x = acc[n][0] + bb.x;
        w0.y = acc[n][1] + bb.y;
        *(float2*)&out[(size_t)r0 * C_DIM + j0 + col] = w0;
        float2 w1;
        w1.x = acc[n][2] + bb.x;
        w1.y = acc[n][3] + bb.y;
        *(float2*)&out[(size_t)(r0 + 8) * C_DIM + j0 + col] = w1;
    }
}

// ---------------- launch ----------------
extern "C" void kernel_launch(void* const* d_in, const int* in_sizes, int n_in,
                              void* d_out, int out_size) {
    (void)in_sizes; (void)n_in; (void)out_size;
    const float* x     = (const float*)d_in[0];
    const float* lat   = (const float*)d_in[1];
    const float* lon   = (const float*)d_in[2];
    const float* w_qkv = (const float*)d_in[3];
    const float* b_qkv = (const float*)d_in[4];
    const float* w_out = (const float*)d_in[5];
    const float* b_out = (const float*)d_in[6];
    float* out = (float*)d_out;

    init_kernel<<<1, 1>>>();
    cvt_kernel<<<3072, 256>>>(x, w_qkv, w_out);
    trig_kernel<<<N_TOK / 256, 256>>>(lat, lon);
    dist_kernel<<<N_TOK, 256>>>();
    finalize_kernel<<<1, 1>>>();

    cudaFuncSetAttribute(qkv_gemm_h, cudaFuncAttributeMaxDynamicSharedMemorySize, PROJ_SMEM_BYTES);
    qkv_gemm_h<<<dim3(3 * C_DIM / 64, N_TOK / 128), 256, PROJ_SMEM_BYTES>>>(b_qkv);

    cudaFuncSetAttribute(attn_mma, cudaFuncAttributeMaxDynamicSharedMemorySize, ATTN_SMEM_BYTES);
    attn_mma<<<dim3(N_TOK / 128, NH), 256, ATTN_SMEM_BYTES>>>();

    cudaFuncSetAttribute(out_gemm_h, cudaFuncAttributeMaxDynamicSharedMemorySize, PROJ_SMEM_BYTES);
    out_gemm_h<<<dim3(C_DIM / 64, N_TOK / 128), 256, PROJ_SMEM_BYTES>>>(b_out, out);
}

// round 15
// speedup vs baseline: 5.3389x; 1.1784x over previous
#include <cuda_runtime.h>
#include <cuda_fp16.h>
#include <math.h>
#include <stdint.h>

// Problem dims
#define N_TOK 4096
#define C_DIM 512
#define NH 8
#define DH 64
#define L2E 1.44269504f

// ---------------- scratch (device globals, no runtime alloc) ----------------
__device__ float  g_dist[(size_t)N_TOK * N_TOK];   // 64 MB haversine distances
__device__ __half g_xh[N_TOK * C_DIM];             // X in fp16
__device__ __half g_wqh[3 * C_DIM * C_DIM];        // w_qkv in fp16
__device__ __half g_woh[C_DIM * C_DIM];            // w_out in fp16
__device__ __half g_q[NH * N_TOK * DH];            // head-major [h][n][d], q scaled by L2E/8
__device__ __half g_k[NH * N_TOK * DH];
__device__ __half g_v[NH * N_TOK * DH];
__device__ __half g_o[NH * N_TOK * DH];            // attention output (fp16)
__device__ float4 g_trigA[N_TOK];                  // {sin(lat/2), cos(lat/2), sin(lon/2), cos(lon/2)}
__device__ float  g_clat[N_TOK];                   // cos(lat)
__device__ double g_sum;
__device__ double g_sumsq;
__device__ float  g_neg_inv_std;                   // includes L2E factor

// ---------------- helpers ----------------
__device__ __forceinline__ void mma16(float c[4], const uint32_t a[4], uint32_t b0, uint32_t b1) {
    asm volatile(
        "mma.sync.aligned.m16n8k16.row.col.f32.f16.f16.f32 "
        "{%0,%1,%2,%3}, {%4,%5,%6,%7}, {%8,%9}, {%0,%1,%2,%3};"
        : "+f"(c[0]), "+f"(c[1]), "+f"(c[2]), "+f"(c[3])
        : "r"(a[0]), "r"(a[1]), "r"(a[2]), "r"(a[3]), "r"(b0), "r"(b1));
}
__device__ __forceinline__ void ldsm4(uint32_t r[4], uint32_t addr) {
    asm volatile("ldmatrix.sync.aligned.m8n8.x4.shared.b16 {%0,%1,%2,%3}, [%4];"
        : "=r"(r[0]), "=r"(r[1]), "=r"(r[2]), "=r"(r[3]) : "r"(addr));
}
__device__ __forceinline__ void ldsm4t(uint32_t r[4], uint32_t addr) {
    asm volatile("ldmatrix.sync.aligned.m8n8.x4.trans.shared.b16 {%0,%1,%2,%3}, [%4];"
        : "=r"(r[0]), "=r"(r[1]), "=r"(r[2]), "=r"(r[3]) : "r"(addr));
}
__device__ __forceinline__ uint32_t smem_u32(const void* p) {
    uint32_t a;
    asm("{ .reg .u64 t; cvta.to.shared.u64 t, %1; cvt.u32.u64 %0, t; }" : "=r"(a) : "l"(p));
    return a;
}
__device__ __forceinline__ void cpa16(uint32_t s, const void* g) {
    asm volatile("cp.async.cg.shared.global [%0], [%1], 16;" :: "r"(s), "l"(g));
}
#define CP_COMMIT() asm volatile("cp.async.commit_group;" ::: "memory")
#define CP_WAIT(n)  asm volatile("cp.async.wait_group %0;" :: "n"(n) : "memory")

__device__ __forceinline__ uint32_t packh2(float a, float b) {
    __half2 h = __floats2half2_rn(a, b);
    return *(uint32_t*)&h;
}
__device__ __forceinline__ float ex2(float x) {
    float y;
    asm("ex2.approx.ftz.f32 %0, %1;" : "=f"(y) : "f"(x));
    return y;
}

// ---------------- kernel 0b: fp16 conversion of X, w_qkv, w_out ----------------
__global__ void cvt_kernel(const float* __restrict__ x,
                           const float* __restrict__ wq,
                           const float* __restrict__ wo) {
    int idx = blockIdx.x * 256 + threadIdx.x;
    const float4* src;
    uint2* dst;
    if (idx < 524288) {
        src = (const float4*)x + idx;
        dst = (uint2*)g_xh + idx;
    } else if (idx < 524288 + 196608) {
        src = (const float4*)wq + (idx - 524288);
        dst = (uint2*)g_wqh + (idx - 524288);
    } else {
        src = (const float4*)wo + (idx - 720896);
        dst = (uint2*)g_woh + (idx - 720896);
    }
    float4 v = *src;
    uint2 o;
    o.x = packh2(v.x, v.y);
    o.y = packh2(v.z, v.w);
    *dst = o;
}

// ---------------- kernel 0c: trig precompute (+ accumulator init) ----------------
__global__ void trig_kernel(const float* __restrict__ lat, const float* __restrict__ lon) {
    if (blockIdx.x == 0 && threadIdx.x == 0) {
        g_sum = 0.0;
        g_sumsq = 0.0;
    }
    int j = blockIdx.x * 256 + threadIdx.x;
    float la = lat[j], lo = lon[j];
    float sh, ch, so, co;
    __sincosf(la * 0.5f, &sh, &ch);
    __sincosf(lo * 0.5f, &so, &co);
    g_trigA[j] = make_float4(sh, ch, so, co);
    g_clat[j] = __cosf(la);
}

// ---------------- kernel 1: symmetric haversine distance (upper-tri tiles) ----------------
// 64x64 tiles, only bi<=bj computed; off-diag written twice (tile + transpose).
// Grid: 64*65/2 = 2080 blocks, 256 threads.
#define NTILE 64
__global__ void dist_kernel2() {
    __shared__ float tile[64][65];
    __shared__ float4 tI[64];
    __shared__ float  cI[64];
    __shared__ float4 tJ[64];
    __shared__ float  cJ[64];
    __shared__ double shs[256];
    __shared__ double shs2[256];

    int p = blockIdx.x;
    // decode triangular pair (bi <= bj): start(bi) = bi*64 - bi*(bi-1)/2
    int bi = (int)((129.0f - sqrtf(16641.0f - 8.0f * (float)p)) * 0.5f);
    if (bi < 0) bi = 0;
    if (bi > 63) bi = 63;
    while (bi > 0 && bi * 64 - bi * (bi - 1) / 2 > p) bi--;
    while (bi < 63 && (bi + 1) * 64 - (bi + 1) * bi / 2 <= p) bi++;
    int bj = bi + (p - (bi * 64 - bi * (bi - 1) / 2));
    int i0 = bi * 64, j0 = bj * 64;

    int tid = threadIdx.x;
    if (tid < 64) {
        tI[tid] = g_trigA[i0 + tid];
        cI[tid] = g_clat[i0 + tid];
    } else if (tid < 128) {
        int t = tid - 64;
        tJ[t] = g_trigA[j0 + t];
        cJ[t] = g_clat[j0 + t];
    }
    __syncthreads();

    int c4 = (tid & 15) * 4;
    int r0 = tid >> 4;          // 0..15
    double s = 0.0, s2 = 0.0;

#pragma unroll
    for (int rr = 0; rr < 4; rr++) {
        int row = r0 + rr * 16;
        float4 ti = tI[row];
        float cli = cI[row];
        float4 v;
        float dv[4];
#pragma unroll
        for (int cc = 0; cc < 4; cc++) {
            int col = c4 + cc;
            float4 tj = tJ[col];
            float clj = cJ[col];
            float sdlat = ti.x * tj.y - ti.y * tj.x;
            float sdlon = ti.z * tj.w - ti.w * tj.z;
            float a = sdlat * sdlat + cli * clj * (sdlon * sdlon);
            a = fminf(fmaxf(a, 0.0f), 1.0f);
            float d = 2.0f * asinf(sqrtf(a));
            dv[cc] = d;
            tile[row][col] = d;
            s += (double)d;
            s2 += (double)d * (double)d;
        }
        v.x = dv[0]; v.y = dv[1]; v.z = dv[2]; v.w = dv[3];
        *(float4*)&g_dist[(size_t)(i0 + row) * N_TOK + j0 + c4] = v;
    }

    if (bi != bj) { s *= 2.0; s2 *= 2.0; }
    shs[tid] = s;
    shs2[tid] = s2;
    __syncthreads();

    // transpose write for off-diagonal tiles
    if (bi != bj) {
#pragma unroll
        for (int rr = 0; rr < 4; rr++) {
            int row = r0 + rr * 16;      // row within J tile = output row j0+row
            float4 v;
            v.x = tile[c4 + 0][row];
            v.y = tile[c4 + 1][row];
            v.z = tile[c4 + 2][row];
            v.w = tile[c4 + 3][row];
            *(float4*)&g_dist[(size_t)(j0 + row) * N_TOK + i0 + c4] = v;
        }
    }

    // block reduce
    for (int off = 128; off > 0; off >>= 1) {
        if (tid < off) {
            shs[tid] += shs[tid + off];
            shs2[tid] += shs2[tid + off];
        }
        __syncthreads();
    }
    if (tid == 0) {
        atomicAdd(&g_sum, shs[0]);
        atomicAdd(&g_sumsq, shs2[0]);
    }
}

// ---------------- kernel 2: finalize std (ddof=1), fold log2e ----------------
__global__ void finalize_kernel() {
    double M = (double)N_TOK * (double)N_TOK;
    double mean = g_sum / M;
    double var = (g_sumsq - g_sum * mean) / (M - 1.0);
    g_neg_inv_std = (float)(-(double)L2E / sqrt(var));
}

// ====== fp16 GEMM tile geometry (shared by qkv/out projections) ======
#define ROWB 144
#define PA0_B 0
#define PA1_B 18432
#define PB0_B 36864
#define PB1_B 46080
#define PROJ_SMEM_BYTES 55296

// ---------------- kernel 3: QKV projection (fp16 mma) ----------------
__global__ void __launch_bounds__(256, 2) qkv_gemm_h(const float* __restrict__ bq) {
    extern __shared__ char smem[];
    uint32_t sbase = smem_u32(smem);
    int j0 = blockIdx.x * 64;
    int i0 = blockIdx.y * 128;
    int tid = threadIdx.x;
    int warp = tid >> 5;
    int lane = tid & 31;
    int gid = lane >> 2;
    int tig = lane & 3;
    int w16 = warp * 16;
    int l15 = lane & 15;
    int lhi = (lane >> 4) * 16;
    int l7 = lane & 7;
    int r16 = (lane & 16) ? 8 : 0;
    int b8 = (lane & 8) ? 16 : 0;

    const __half* Ag = g_xh + (size_t)i0 * C_DIM;
    const __half* Bg = g_wqh + (size_t)j0 * C_DIM;

#pragma unroll
    for (int t = 0; t < 4; t++) {
        int id = tid + t * 256;
        int r = id >> 3, c = id & 7;
        cpa16(sbase + PA0_B + r * ROWB + c * 16, Ag + (size_t)r * C_DIM + c * 8);
    }
#pragma unroll
    for (int t = 0; t < 2; t++) {
        int id = tid + t * 256;
        int r = id >> 3, c = id & 7;
        cpa16(sbase + PB0_B + r * ROWB + c * 16, Bg + (size_t)r * C_DIM + c * 8);
    }
    CP_COMMIT();

    float acc[8][4];
#pragma unroll
    for (int n = 0; n < 8; n++)
#pragma unroll
        for (int q = 0; q < 4; q++) acc[n][q] = 0.0f;

    for (int kc = 0; kc < 8; kc++) {
        int cur = kc & 1;
        uint32_t Ac = sbase + (cur ? PA1_B : PA0_B);
        uint32_t Bc = sbase + (cur ? PB1_B : PB0_B);
        __syncthreads();
        if (kc + 1 < 8) {
            uint32_t An = sbase + (cur ? PA0_B : PA1_B);
            uint32_t Bn = sbase + (cur ? PB0_B : PB1_B);
            int ko = (kc + 1) * 64;
#pragma unroll
            for (int t = 0; t < 4; t++) {
                int id = tid + t * 256;
                int r = id >> 3, c = id & 7;
                cpa16(An + r * ROWB + c * 16, Ag + (size_t)r * C_DIM + ko + c * 8);
            }
#pragma unroll
            for (int t = 0; t < 2; t++) {
                int id = tid + t * 256;
                int r = id >> 3, c = id & 7;
                cpa16(Bn + r * ROWB + c * 16, Bg + (size_t)r * C_DIM + ko + c * 8);
            }
            CP_COMMIT();
            CP_WAIT(1);
        } else {
            CP_WAIT(0);
        }
        __syncthreads();

#pragma unroll
        for (int k = 0; k < 4; k++) {
            uint32_t a[4];
            ldsm4(a, Ac + (w16 + l15) * ROWB + k * 32 + lhi);
#pragma unroll
            for (int np = 0; np < 4; np++) {
                uint32_t b[4];
                ldsm4(b, Bc + (np * 16 + r16 + l7) * ROWB + k * 32 + b8);
                mma16(acc[2 * np], a, b[0], b[1]);
                mma16(acc[2 * np + 1], a, b[2], b[3]);
            }
        }
    }

    int part = j0 / C_DIM;
    int h = (j0 % C_DIM) / DH;
    __half* dst = (part == 0) ? g_q : ((part == 1) ? g_k : g_v);
    float sc = (part == 0) ? (0.125f * L2E) : 1.0f;
    dst += (size_t)h * N_TOK * DH;
#pragma unroll
    for (int n = 0; n < 8; n++) {
        int col = n * 8 + 2 * tig;
        float2 bb = *(const float2*)&bq[j0 + col];
        int r0 = i0 + w16 + gid;
        *(uint32_t*)&dst[(size_t)r0 * DH + col] =
            packh2((acc[n][0] + bb.x) * sc, (acc[n][1] + bb.y) * sc);
        *(uint32_t*)&dst[(size_t)(r0 + 8) * DH + col] =
            packh2((acc[n][2] + bb.x) * sc, (acc[n][3] + bb.y) * sc);
    }
}

// ---------------- kernel 4: flash attention (fp16 mma, exp2 domain) ----------------
#define QS_B 0
#define K0_B 18432
#define V0_B (18432 + 9216)
#define K1_B (18432 + 2 * 9216)
#define V1_B (18432 + 3 * 9216)
#define ATTN_SMEM_BYTES (18432 + 4 * 9216)

__global__ void __launch_bounds__(256, 2) attn_mma() {
    extern __shared__ char smem[];
    uint32_t sbase = smem_u32(smem);

    int tid = threadIdx.x;
    int warp = tid >> 5;
    int lane = tid & 31;
    int gid = lane >> 2;
    int tig = lane & 3;
    int w16 = warp * 16;
    int h = blockIdx.y;
    int i0 = blockIdx.x * 128;
    float nis = g_neg_inv_std;

    const __half* Qg = g_q + (size_t)h * N_TOK * DH + (size_t)i0 * DH;
    const __half* Kg = g_k + (size_t)h * N_TOK * DH;
    const __half* Vg = g_v + (size_t)h * N_TOK * DH;

    int l15 = lane & 15;
    int lhi = (lane >> 4) * 16;
    int l7 = lane & 7;
    int r16 = (lane & 16) ? 8 : 0;
    int b8 = (lane & 8) ? 16 : 0;

#pragma unroll
    for (int t = 0; t < 4; t++) {
        int id = tid + t * 256;
        int r = id >> 3, c = id & 7;
        cpa16(sbase + QS_B + r * ROWB + c * 16, Qg + r * DH + c * 8);
    }
#pragma unroll
    for (int t = 0; t < 2; t++) {
        int id = tid + t * 256;
        int r = id >> 3, c = id & 7;
        cpa16(sbase + K0_B + r * ROWB + c * 16, Kg + r * DH + c * 8);
        cpa16(sbase + V0_B + r * ROWB + c * 16, Vg + r * DH + c * 8);
    }
    CP_COMMIT();

    float m0 = -INFINITY, m1 = -INFINITY, l0 = 0.0f, l1 = 0.0f;
    float o[8][4];
#pragma unroll
    for (int n = 0; n < 8; n++)
#pragma unroll
        for (int q = 0; q < 4; q++) o[n][q] = 0.0f;

    const float* d0base = g_dist + (size_t)(i0 + w16 + gid) * N_TOK + 2 * tig;
    const float* d1base = d0base + (size_t)8 * N_TOK;

    for (int kb = 0; kb < N_TOK / 64; kb++) {
        int j0 = kb * 64;
        int cur = kb & 1;
        uint32_t Kc = sbase + (cur ? K1_B : K0_B);
        uint32_t Vc = sbase + (cur ? V1_B : V0_B);

        float2 bx0[8], bx1[8];
#pragma unroll
        for (int n = 0; n < 8; n++) {
            bx0[n] = *(const float2*)(d0base + j0 + n * 8);
            bx1[n] = *(const float2*)(d1base + j0 + n * 8);
        }

        __syncthreads();
        if (kb + 1 < N_TOK / 64) {
            uint32_t Kn = sbase + (cur ? K0_B : K1_B);
            uint32_t Vn = sbase + (cur ? V0_B : V1_B);
            const __half* Kgn = Kg + (size_t)(j0 + 64) * DH;
            const __half* Vgn = Vg + (size_t)(j0 + 64) * DH;
#pragma unroll
            for (int t = 0; t < 2; t++) {
                int id = tid + t * 256;
                int r = id >> 3, c = id & 7;
                cpa16(Kn + r * ROWB + c * 16, Kgn + r * DH + c * 8);
                cpa16(Vn + r * ROWB + c * 16, Vgn + r * DH + c * 8);
            }
            CP_COMMIT();
            CP_WAIT(1);
        } else {
            CP_WAIT(0);
        }
        __syncthreads();

        float s[8][4];
#pragma unroll
        for (int n = 0; n < 8; n++)
#pragma unroll
            for (int q = 0; q < 4; q++) s[n][q] = 0.0f;

#pragma unroll
        for (int k = 0; k < 4; k++) {
            uint32_t a[4];
            ldsm4(a, sbase + QS_B + (w16 + l15) * ROWB + k * 32 + lhi);
#pragma unroll
            for (int np = 0; np < 4; np++) {
                uint32_t b[4];
                ldsm4(b, Kc + (np * 16 + r16 + l7) * ROWB + k * 32 + b8);
                mma16(s[2 * np], a, b[0], b[1]);
                mma16(s[2 * np + 1], a, b[2], b[3]);
            }
        }

        float mx0 = -INFINITY, mx1 = -INFINITY;
#pragma unroll
        for (int n = 0; n < 8; n++) {
            s[n][0] += bx0[n].x * nis;
            s[n][1] += bx0[n].y * nis;
            s[n][2] += bx1[n].x * nis;
            s[n][3] += bx1[n].y * nis;
            mx0 = fmaxf(mx0, fmaxf(s[n][0], s[n][1]));
            mx1 = fmaxf(mx1, fmaxf(s[n][2], s[n][3]));
        }
        mx0 = fmaxf(mx0, __shfl_xor_sync(0xffffffffu, mx0, 1));
        mx0 = fmaxf(mx0, __shfl_xor_sync(0xffffffffu, mx0, 2));
        mx1 = fmaxf(mx1, __shfl_xor_sync(0xffffffffu, mx1, 1));
        mx1 = fmaxf(mx1, __shfl_xor_sync(0xffffffffu, mx1, 2));

        float mn0 = fmaxf(m0, mx0);
        float mn1 = fmaxf(m1, mx1);
        float f0 = ex2(m0 - mn0);
        float f1 = ex2(m1 - mn1);
        m0 = mn0; m1 = mn1;
        l0 *= f0; l1 *= f1;

        float sum0 = 0.0f, sum1 = 0.0f;
#pragma unroll
        for (int n = 0; n < 8; n++) {
            s[n][0] = ex2(s[n][0] - mn0);
            s[n][1] = ex2(s[n][1] - mn0);
            s[n][2] = ex2(s[n][2] - mn1);
            s[n][3] = ex2(s[n][3] - mn1);
            sum0 += s[n][0] + s[n][1];
            sum1 += s[n][2] + s[n][3];
            o[n][0] *= f0; o[n][1] *= f0;
            o[n][2] *= f1; o[n][3] *= f1;
        }
        l0 += sum0;
        l1 += sum1;

#pragma unroll
        for (int kk = 0; kk < 4; kk++) {
            uint32_t a[4];
            a[0] = packh2(s[2 * kk][0], s[2 * kk][1]);
            a[1] = packh2(s[2 * kk][2], s[2 * kk][3]);
            a[2] = packh2(s[2 * kk + 1][0], s[2 * kk + 1][1]);
            a[3] = packh2(s[2 * kk + 1][2], s[2 * kk + 1][3]);
#pragma unroll
            for (int dp = 0; dp < 4; dp++) {
                uint32_t b[4];
                ldsm4t(b, Vc + (kk * 16 + l15) * ROWB + dp * 32 + lhi);
                mma16(o[2 * dp], a, b[0], b[1]);
                mma16(o[2 * dp + 1], a, b[2], b[3]);
            }
        }
    }

    l0 += __shfl_xor_sync(0xffffffffu, l0, 1);
    l0 += __shfl_xor_sync(0xffffffffu, l0, 2);
    l1 += __shfl_xor_sync(0xffffffffu, l1, 1);
    l1 += __shfl_xor_sync(0xffffffffu, l1, 2);
    float inv0 = 1.0f / l0;
    float inv1 = 1.0f / l1;

    __half* O = g_o + ((size_t)h * N_TOK + i0) * DH;
#pragma unroll
    for (int n = 0; n < 8; n++) {
        int col = n * 8 + 2 * tig;
        *(uint32_t*)&O[(size_t)(w16 + gid) * DH + col] = packh2(o[n][0] * inv0, o[n][1] * inv0);
        *(uint32_t*)&O[(size_t)(w16 + gid + 8) * DH + col] = packh2(o[n][2] * inv1, o[n][3] * inv1);
    }
}

// ---------------- kernel 5: output projection (fp16 mma) ----------------
__global__ void __launch_bounds__(256, 2) out_gemm_h(const float* __restrict__ bo,
                                                     float* __restrict__ out) {
    extern __shared__ char smem[];
    uint32_t sbase = smem_u32(smem);
    int j0 = blockIdx.x * 64;
    int i0 = blockIdx.y * 128;
    int tid = threadIdx.x;
    int warp = tid >> 5;
    int lane = tid & 31;
    int gid = lane >> 2;
    int tig = lane & 3;
    int w16 = warp * 16;
    int l15 = lane & 15;
    int lhi = (lane >> 4) * 16;
    int l7 = lane & 7;
    int r16 = (lane & 16) ? 8 : 0;
    int b8 = (lane & 8) ? 16 : 0;

#pragma unroll
    for (int t = 0; t < 4; t++) {
        int id = tid + t * 256;
        int r = id >> 3, c = id & 7;
        cpa16(sbase + PA0_B + r * ROWB + c * 16, g_o + (size_t)(i0 + r) * DH + c * 8);
    }
#pragma unroll
    for (int t = 0; t < 2; t++) {
        int id = tid + t * 256;
        int r = id >> 3, c = id & 7;
        cpa16(sbase + PB0_B + r * ROWB + c * 16, g_woh + (size_t)(j0 + r) * C_DIM + c * 8);
    }
    CP_COMMIT();

    float acc[8][4];
#pragma unroll
    for (int n = 0; n < 8; n++)
#pragma unroll
        for (int q = 0; q < 4; q++) acc[n][q] = 0.0f;

    for (int kc = 0; kc < 8; kc++) {
        int cur = kc & 1;
        uint32_t Ac = sbase + (cur ? PA1_B : PA0_B);
        uint32_t Bc = sbase + (cur ? PB1_B : PB0_B);
        __syncthreads();
        if (kc + 1 < 8) {
            uint32_t An = sbase + (cur ? PA0_B : PA1_B);
            uint32_t Bn = sbase + (cur ? PB0_B : PB1_B);
            int hn = kc + 1;
            const __half* Agn = g_o + (size_t)hn * N_TOK * DH + (size_t)i0 * DH;
            const __half* Bgn = g_woh + (size_t)j0 * C_DIM + hn * DH;
#pragma unroll
            for (int t = 0; t < 4; t++) {
                int id = tid + t * 256;
                int r = id >> 3, c = id & 7;
                cpa16(An + r * ROWB + c * 16, Agn + (size_t)r * DH + c * 8);
            }
#pragma unroll
            for (int t = 0; t < 2; t++) {
                int id = tid + t * 256;
                int r = id >> 3, c = id & 7;
                cpa16(Bn + r * ROWB + c * 16, Bgn + (size_t)r * C_DIM + c * 8);
            }
            CP_COMMIT();
            CP_WAIT(1);
        } else {
            CP_WAIT(0);
        }
        __syncthreads();

#pragma unroll
        for (int k = 0; k < 4; k++) {
            uint32_t a[4];
            ldsm4(a, Ac + (w16 + l15) * ROWB + k * 32 + lhi);
#pragma unroll
            for (int np = 0; np < 4; np++) {
                uint32_t b[4];
                ldsm4(b, Bc + (np * 16 + r16 + l7) * ROWB + k * 32 + b8);
                mma16(acc[2 * np], a, b[0], b[1]);
                mma16(acc[2 * np + 1], a, b[2], b[3]);
            }
        }
    }

#pragma unroll
    for (int n = 0; n < 8; n++) {
        int col = n * 8 + 2 * tig;
        float2 bb = *(const float2*)&bo[j0 + col];
        int r0 = i0 + w16 + gid;
        float2 w0;
        w0.x = acc[n][0] + bb.x;
        w0.y = acc[n][1] + bb.y;
        *(float2*)&out[(size_t)r0 * C_DIM + j0 + col] = w0;
        float2 w1;
        w1.x = acc[n][2] + bb.x;
        w1.y = acc[n][3] + bb.y;
        *(float2*)&out[(size_t)(r0 + 8) * C_DIM + j0 + col] = w1;
    }
}

// ---------------- launch ----------------
extern "C" void kernel_launch(void* const* d_in, const int* in_sizes, int n_in,
                              void* d_out, int out_size) {
    (void)in_sizes; (void)n_in; (void)out_size;
    const float* x     = (const float*)d_in[0];
    const float* lat   = (const float*)d_in[1];
    const float* lon   = (const float*)d_in[2];
    const float* w_qkv = (const float*)d_in[3];
    const float* b_qkv = (const float*)d_in[4];
    const float* w_out = (const float*)d_in[5];
    const float* b_out = (const float*)d_in[6];
    float* out = (float*)d_out;

    trig_kernel<<<N_TOK / 256, 256>>>(lat, lon);
    cvt_kernel<<<3072, 256>>>(x, w_qkv, w_out);
    dist_kernel2<<<(NTILE * (NTILE + 1)) / 2, 256>>>();
    finalize_kernel<<<1, 1>>>();

    cudaFuncSetAttribute(qkv_gemm_h, cudaFuncAttributeMaxDynamicSharedMemorySize, PROJ_SMEM_BYTES);
    qkv_gemm_h<<<dim3(3 * C_DIM / 64, N_TOK / 128), 256, PROJ_SMEM_BYTES>>>(b_qkv);

    cudaFuncSetAttribute(attn_mma, cudaFuncAttributeMaxDynamicSharedMemorySize, ATTN_SMEM_BYTES);
    attn_mma<<<dim3(N_TOK / 128, NH), 256, ATTN_SMEM_BYTES>>>();

    cudaFuncSetAttribute(out_gemm_h, cudaFuncAttributeMaxDynamicSharedMemorySize, PROJ_SMEM_BYTES);
    out_gemm_h<<<dim3(C_DIM / 64, N_TOK / 128), 256, PROJ_SMEM_BYTES>>>(b_out, out);
}